// round 7
// baseline (speedup 1.0000x reference)
#include <cuda_runtime.h>
#include <cuda_bf16.h>
#include <math.h>

#define S_LEN 2048
#define HID_D 2048
#define NH 16
#define HD 128
#define DR 64
#define DQK 192
#define CKV 512
#define CQ 1536

// ---------------- scratch ----------------------------------------------------
__device__ float g_cKV[S_LEN * CKV];
__device__ float g_cQ [S_LEN * CQ];
__device__ float g_qR [S_LEN * NH * DR];
__device__ float g_kR [S_LEN * DR];
__device__ float g_Vb [NH * S_LEN * HD];      // [h][s][128] f32
__device__ float g_AO [S_LEN * NH * HD];      // [s][h*128+d]
__device__ unsigned short g_QH[NH * S_LEN * DQK];   // k-paired bf16 hi
__device__ unsigned short g_QL[NH * S_LEN * DQK];
__device__ unsigned short g_KH[NH * S_LEN * DQK];
__device__ unsigned short g_KL[NH * S_LEN * DQK];
__device__ unsigned short g_VTH[NH * HD * S_LEN];   // [h][d][s] s-paired
__device__ unsigned short g_VTL[NH * HD * S_LEN];

// pair-permutation within a 16-chunk: (2t,2t+1)->(4t,4t+1), (2t+8,2t+9)->(4t+2,4t+3)
__device__ __forceinline__ int pi16(int c) {
    return (c & 1) + (((c & 7) >> 1) << 2) + ((c >> 3) << 1);
}
__device__ __forceinline__ int pi16e(int c) {
    return (((c & 7) >> 1) << 2) + ((c >> 3) << 1);
}

// ---------------- tf32 helpers ---------------------------------------------
__device__ __forceinline__ unsigned f2tf(float x) {
    unsigned u;
    asm("cvt.rna.tf32.f32 %0, %1;" : "=r"(u) : "f"(x));
    return u;
}

__device__ __forceinline__ void mma8(float c[4], const unsigned a[4], const unsigned b[2]) {
    asm volatile(
        "mma.sync.aligned.m16n8k8.row.col.f32.tf32.tf32.f32 "
        "{%0,%1,%2,%3}, {%4,%5,%6,%7}, {%8,%9}, {%0,%1,%2,%3};\n"
        : "+f"(c[0]), "+f"(c[1]), "+f"(c[2]), "+f"(c[3])
        : "r"(a[0]), "r"(a[1]), "r"(a[2]), "r"(a[3]), "r"(b[0]), "r"(b[1]));
}

// ---------------- bf16 helpers ----------------------------------------------
__device__ __forceinline__ void mma16(float c[4], const unsigned a[4], const unsigned b[2]) {
    asm volatile(
        "mma.sync.aligned.m16n8k16.row.col.f32.bf16.bf16.f32 "
        "{%0,%1,%2,%3}, {%4,%5,%6,%7}, {%8,%9}, {%0,%1,%2,%3};\n"
        : "+f"(c[0]), "+f"(c[1]), "+f"(c[2]), "+f"(c[3])
        : "r"(a[0]), "r"(a[1]), "r"(a[2]), "r"(a[3]), "r"(b[0]), "r"(b[1]));
}

__device__ __forceinline__ void split2(float x, unsigned short &hh, unsigned short &ll) {
    __nv_bfloat16 bh = __float2bfloat16(x);
    float hf = __bfloat162float(bh);
    __nv_bfloat16 bl = __float2bfloat16(x - hf);
    hh = __bfloat16_as_ushort(bh);
    ll = __bfloat16_as_ushort(bl);
}

__device__ __forceinline__ unsigned bfbits(float x) {
    return (unsigned)__bfloat16_as_ushort(__float2bfloat16(x));
}
__device__ __forceinline__ float bfval(float x) {
    return __bfloat162float(__float2bfloat16(x));
}
__device__ __forceinline__ unsigned packsplit(float x, float y, unsigned &lo) {
    float xh = bfval(x), yh = bfval(y);
    unsigned hi = bfbits(x) | (bfbits(y) << 16);
    lo = bfbits(x - xh) | (bfbits(y - yh) << 16);
    return hi;
}

// ---------------- grouped tf32 tensor-core GEMM -----------------------------
struct GroupArgs {
    const float* A[4];
    const float* B[4];
    void*        C[4];
    void*        Clo[4];
    int K[4];
    int N[4];
    int mode[4];
    int tstart[5];
};

__global__ __launch_bounds__(256, 2)
void mma_gemm_grouped(GroupArgs ga)
{
    __shared__ unsigned As[2][128][20];
    __shared__ unsigned Bs[2][16][136];

    int g = 0;
    while (blockIdx.y >= (unsigned)ga.tstart[g + 1]) g++;
    const float* __restrict__ A = ga.A[g];
    const float* __restrict__ B = ga.B[g];
    const int K = ga.K[g];
    const int N = ga.N[g];
    const int mode = ga.mode[g];

    const int tid  = threadIdx.x;
    const int lane = tid & 31;
    const int warp = tid >> 5;
    const int wm   = warp & 1;
    const int wn   = warp >> 1;
    const int m0   = blockIdx.x * 128;
    const int n0   = (blockIdx.y - ga.tstart[g]) * 128;
    const int fr   = lane >> 2;
    const int fc   = lane & 3;

    float acc[4][4][4];
#pragma unroll
    for (int mt = 0; mt < 4; mt++)
#pragma unroll
        for (int nt = 0; nt < 4; nt++)
#pragma unroll
            for (int i = 0; i < 4; i++) acc[mt][nt][i] = 0.f;

    float4 ra[2], rb[2];

    const int rowA0 = (tid + 0)   >> 2;   const int kcA0 = ((tid + 0)   & 3) * 4;
    const int rowA1 = (tid + 256) >> 2;   const int kcA1 = ((tid + 256) & 3) * 4;
    const int kkB0  = (tid + 0)   >> 5;   const int c4B0 = ((tid + 0)   & 31) * 4;
    const int kkB1  = (tid + 256) >> 5;   const int c4B1 = ((tid + 256) & 31) * 4;

#define LDG_TILE(k0)                                                            \
    {                                                                           \
        ra[0] = *(const float4*)&A[(size_t)(m0 + rowA0) * K + (k0) + kcA0];     \
        ra[1] = *(const float4*)&A[(size_t)(m0 + rowA1) * K + (k0) + kcA1];     \
        if (n0 + c4B0 < N)                                                      \
            rb[0] = *(const float4*)&B[(size_t)((k0) + kkB0) * N + n0 + c4B0];  \
        else rb[0] = make_float4(0.f, 0.f, 0.f, 0.f);                           \
        if (n0 + c4B1 < N)                                                      \
            rb[1] = *(const float4*)&B[(size_t)((k0) + kkB1) * N + n0 + c4B1];  \
        else rb[1] = make_float4(0.f, 0.f, 0.f, 0.f);                           \
    }

#define STS_TILE(buf)                                                           \
    {                                                                           \
        uint4 ua0 = make_uint4(f2tf(ra[0].x), f2tf(ra[0].y), f2tf(ra[0].z), f2tf(ra[0].w)); \
        uint4 ua1 = make_uint4(f2tf(ra[1].x), f2tf(ra[1].y), f2tf(ra[1].z), f2tf(ra[1].w)); \
        *(uint4*)&As[buf][rowA0][kcA0] = ua0;                                   \
        *(uint4*)&As[buf][rowA1][kcA1] = ua1;                                   \
        uint4 ub0 = make_uint4(f2tf(rb[0].x), f2tf(rb[0].y), f2tf(rb[0].z), f2tf(rb[0].w)); \
        uint4 ub1 = make_uint4(f2tf(rb[1].x), f2tf(rb[1].y), f2tf(rb[1].z), f2tf(rb[1].w)); \
        *(uint4*)&Bs[buf][kkB0][c4B0] = ub0;                                    \
        *(uint4*)&Bs[buf][kkB1][c4B1] = ub1;                                    \
    }

#define COMPUTE(buf)                                                            \
    {                                                                           \
        _Pragma("unroll")                                                       \
        for (int ks = 0; ks < 2; ks++) {                                        \
            unsigned af[4][4], bf[4][2];                                        \
            _Pragma("unroll")                                                   \
            for (int mt = 0; mt < 4; mt++) {                                    \
                int mr = wm * 64 + mt * 16 + fr;                                \
                af[mt][0] = As[buf][mr    ][ks * 8 + fc];                       \
                af[mt][1] = As[buf][mr + 8][ks * 8 + fc];                       \
                af[mt][2] = As[buf][mr    ][ks * 8 + fc + 4];                   \
                af[mt][3] = As[buf][mr + 8][ks * 8 + fc + 4];                   \
            }                                                                   \
            _Pragma("unroll")                                                   \
            for (int nt = 0; nt < 4; nt++) {                                    \
                int nc = wn * 32 + nt * 8 + fr;                                 \
                bf[nt][0] = Bs[buf][ks * 8 + fc    ][nc];                       \
                bf[nt][1] = Bs[buf][ks * 8 + fc + 4][nc];                       \
            }                                                                   \
            _Pragma("unroll")                                                   \
            for (int mt = 0; mt < 4; mt++)                                      \
                _Pragma("unroll")                                               \
                for (int nt = 0; nt < 4; nt++)                                  \
                    mma8(acc[mt][nt], af[mt], bf[nt]);                          \
        }                                                                       \
    }

    LDG_TILE(0);
    STS_TILE(0);
    __syncthreads();

    int buf = 0;
#pragma unroll 1
    for (int k0 = 16; k0 < K; k0 += 16) {
        LDG_TILE(k0);
        COMPUTE(buf);
        STS_TILE(buf ^ 1);
        __syncthreads();
        buf ^= 1;
    }
    COMPUTE(buf);

#pragma unroll
    for (int mt = 0; mt < 4; mt++) {
#pragma unroll
        for (int nt = 0; nt < 4; nt++) {
            int row = m0 + wm * 64 + mt * 16 + fr;
            int col = n0 + wn * 32 + nt * 8 + fc * 2;
            if (mode == 0) {
                float* Cf = (float*)ga.C[g];
                if (col < N) {
                    *(float2*)&Cf[(size_t)row * N + col] =
                        make_float2(acc[mt][nt][0], acc[mt][nt][1]);
                    *(float2*)&Cf[(size_t)(row + 8) * N + col] =
                        make_float2(acc[mt][nt][2], acc[mt][nt][3]);
                }
            } else if (mode == 1) {
                unsigned short* CH = (unsigned short*)ga.C[g];
                unsigned short* CL = (unsigned short*)ga.Clo[g];
                int hh = col >> 7, d = col & 127;
                int dp = (d & ~15) | pi16e(d & 15);
                size_t b0 = ((size_t)(hh * S_LEN + row)) * DQK + dp;
                size_t b1 = ((size_t)(hh * S_LEN + row + 8)) * DQK + dp;
                unsigned lo, hi;
                hi = packsplit(acc[mt][nt][0], acc[mt][nt][1], lo);
                *(unsigned*)&CH[b0] = hi; *(unsigned*)&CL[b0] = lo;
                hi = packsplit(acc[mt][nt][2], acc[mt][nt][3], lo);
                *(unsigned*)&CH[b1] = hi; *(unsigned*)&CL[b1] = lo;
            } else {
                float* Cf = (float*)ga.C[g];
                int hh = col >> 7, d = col & 127;
                *(float2*)&Cf[(size_t)((hh * S_LEN) + row)     * HD + d] =
                    make_float2(acc[mt][nt][0], acc[mt][nt][1]);
                *(float2*)&Cf[(size_t)((hh * S_LEN) + row + 8) * HD + d] =
                    make_float2(acc[mt][nt][2], acc[mt][nt][3]);
            }
        }
    }
#undef LDG_TILE
#undef STS_TILE
#undef COMPUTE
}

// ---------------- fused prep: rope_q + rope_k + vtrans -----------------------
// blocks [0,4096): rope_q; [4096,4352): rope_k; [4352,5376): vtrans (32-row tiles)
__global__ __launch_bounds__(256)
void prep_kernel()
{
    const int bid = blockIdx.x;
    const int tid = threadIdx.x;

    if (bid < 4096) {
        int idx = bid * 256 + tid;
        int i = idx & 31;
        int h = (idx >> 5) & 15;
        int t = idx >> 9;
        float invf = powf(10000.0f, -(2.0f * i) / 64.0f);
        float ang = (float)t * invf;
        float s, c;
        sincosf(ang, &s, &c);
        const float* x = g_qR + (size_t)t * (NH * DR) + h * DR;
        float x1 = x[i], x2 = x[i + 32];
        float r1 = x1 * c - x2 * s;
        float r2 = x2 * c + x1 * s;
        size_t base = ((size_t)(h * S_LEN + t)) * DQK;
        int d1 = 128 + i, d2 = 160 + i;
        int d1p = (d1 & ~15) | pi16(d1 & 15);
        int d2p = (d2 & ~15) | pi16(d2 & 15);
        unsigned short hh, ll;
        split2(r1, hh, ll); g_QH[base + d1p] = hh; g_QL[base + d1p] = ll;
        split2(r2, hh, ll); g_QH[base + d2p] = hh; g_QL[base + d2p] = ll;
    } else if (bid < 4352) {
        int idx = (bid - 4096) * 256 + tid;
        int i = idx & 31;
        int t = idx >> 5;
        float invf = powf(10000.0f, -(2.0f * i) / 64.0f);
        float ang = (float)t * invf;
        float s, c;
        sincosf(ang, &s, &c);
        const float* x = g_kR + (size_t)t * DR;
        float r1 = x[i] * c - x[i + 32] * s;
        float r2 = x[i + 32] * c + x[i] * s;
        unsigned short h1, l1, h2, l2;
        split2(r1, h1, l1);
        split2(r2, h2, l2);
        int d1 = 128 + i, d2 = 160 + i;
        int d1p = (d1 & ~15) | pi16(d1 & 15);
        int d2p = (d2 & ~15) | pi16(d2 & 15);
#pragma unroll
        for (int h = 0; h < NH; h++) {
            size_t base = ((size_t)(h * S_LEN + t)) * DQK;
            g_KH[base + d1p] = h1; g_KL[base + d1p] = l1;
            g_KH[base + d2p] = h2; g_KL[base + d2p] = l2;
        }
    } else {
        // vtrans, 32 s-rows per block: smem 17KB (keeps rope blocks at full occupancy)
        __shared__ float sv[32][133];
        int vb = bid - 4352;
        int h  = vb >> 6;
        int s0 = (vb & 63) * 32;
        const float* src = g_Vb + ((size_t)h * S_LEN + s0) * HD;
#pragma unroll
        for (int i = 0; i < 4; i++) {
            int idx = tid + i * 256;
            int r = idx >> 5, c4 = (idx & 31) * 4;
            float4 v = *(const float4*)&src[r * HD + c4];
            sv[r][c4] = v.x; sv[r][c4 + 1] = v.y; sv[r][c4 + 2] = v.z; sv[r][c4 + 3] = v.w;
        }
        __syncthreads();
        int sl = tid & 31, d0 = tid >> 5;    // d0 0..7
        int sp = s0 + ((sl & ~15) | pi16(sl & 15));
#pragma unroll
        for (int dd = 0; dd < 16; dd++) {
            int d = d0 * 16 + dd;
            unsigned short hh, ll;
            split2(sv[sl][d], hh, ll);
            size_t o = ((size_t)(h * HD + d)) * S_LEN + sp;
            g_VTH[o] = hh;
            g_VTL[o] = ll;
        }
    }
}

// ---------------- bf16x3 tensor-core flash attention -------------------------
// smem (bytes): QH[128][208]@0, QL@53248, KH[64][208]@106496 (reused as PH[128][80]),
// KL@133120 (reused as PL[128][80]), VTH[128][80]@159744, VTL@180224, red@200704
#define ATTN_SMEM 201728

__global__ __launch_bounds__(256, 1)
void attn_mma_kernel()
{
    extern __shared__ char smraw[];
    unsigned short* QH  = (unsigned short*)(smraw);
    unsigned short* QL  = (unsigned short*)(smraw + 53248);
    unsigned short* KH  = (unsigned short*)(smraw + 106496);
    unsigned short* KL  = (unsigned short*)(smraw + 133120);
    unsigned short* VTH = (unsigned short*)(smraw + 159744);
    unsigned short* VTL = (unsigned short*)(smraw + 180224);
    float* red = (float*)(smraw + 200704);

    const int bid  = blockIdx.x;
    const int mb   = 15 - (bid >> 4);
    const int h    = bid & 15;
    const int m0   = mb * 128;
    const int tid  = threadIdx.x;
    const int lane = tid & 31;
    const int warp = tid >> 5;
    const int wm = warp >> 1, wn = warp & 1;
    const int g = lane >> 2, t = lane & 3;

    // stage Q
    {
        const uint4* sH = (const uint4*)(g_QH + ((size_t)h * S_LEN + m0) * DQK);
        const uint4* sL = (const uint4*)(g_QL + ((size_t)h * S_LEN + m0) * DQK);
        uint4* dH = (uint4*)QH;
        uint4* dL = (uint4*)QL;
#pragma unroll
        for (int i = 0; i < 12; i++) {
            int idx = tid + i * 256;
            int r = idx / 24, u = idx - r * 24;
            dH[r * 26 + u] = sH[idx];
            dL[r * 26 + u] = sL[idx];
        }
    }

    float oacc[2][8][4];
#pragma unroll
    for (int mt = 0; mt < 2; mt++)
#pragma unroll
        for (int nt = 0; nt < 8; nt++)
#pragma unroll
            for (int c = 0; c < 4; c++) oacc[mt][nt][c] = 0.f;

    float mrow[2][2] = {{-1e30f, -1e30f}, {-1e30f, -1e30f}};
    float lrow[2][2] = {{0.f, 0.f}, {0.f, 0.f}};

    const float scale = 0.07216878364870322f;
    const int ntiles = 2 * mb + 2;

    const uint4* KHg = (const uint4*)(g_KH + (size_t)h * S_LEN * DQK);
    const uint4* KLg = (const uint4*)(g_KL + (size_t)h * S_LEN * DQK);
    const uint4* VHg = (const uint4*)(g_VTH + (size_t)h * HD * S_LEN);
    const uint4* VLg = (const uint4*)(g_VTL + (size_t)h * HD * S_LEN);
    uint4* KH4 = (uint4*)KH;
    uint4* KL4 = (uint4*)KL;
    uint4* VH4 = (uint4*)VTH;
    uint4* VL4 = (uint4*)VTL;

#pragma unroll 1
    for (int tile = 0; tile < ntiles; tile++) {
        const int n0 = tile * 64;
        __syncthreads();   // K/V/P consumed; safe to restage

        {
            const uint4* sH = KHg + (size_t)n0 * 24;
            const uint4* sL = KLg + (size_t)n0 * 24;
#pragma unroll
            for (int i = 0; i < 6; i++) {
                int idx = tid + i * 256;
                int r = idx / 24, u = idx - r * 24;
                KH4[r * 26 + u] = sH[idx];
                KL4[r * 26 + u] = sL[idx];
            }
        }
        {
            const uint4* sH = VHg + (n0 >> 3);
            const uint4* sL = VLg + (n0 >> 3);
#pragma unroll
            for (int i = 0; i < 4; i++) {
                int idx = tid + i * 256;
                int d = idx >> 3, u = idx & 7;
                VH4[d * 10 + u] = sH[d * 256 + u];
                VL4[d * 10 + u] = sL[d * 256 + u];
            }
        }
        __syncthreads();

        // ---- S = Q K^T ----
        float sacc[2][4][4];
#pragma unroll
        for (int mt = 0; mt < 2; mt++)
#pragma unroll
            for (int nt = 0; nt < 4; nt++)
#pragma unroll
                for (int c = 0; c < 4; c++) sacc[mt][nt][c] = 0.f;

#pragma unroll
        for (int kt = 0; kt < 12; kt++) {
            unsigned ah[2][4], al[2][4];
#pragma unroll
            for (int mt = 0; mt < 2; mt++) {
                int rb = (wm * 32 + mt * 16 + g) * 208 + kt * 16 + 4 * t;
                uint2 a0 = *(const uint2*)&QH[rb];
                uint2 a1 = *(const uint2*)&QH[rb + 8 * 208];
                ah[mt][0] = a0.x; ah[mt][1] = a1.x; ah[mt][2] = a0.y; ah[mt][3] = a1.y;
                uint2 b0 = *(const uint2*)&QL[rb];
                uint2 b1 = *(const uint2*)&QL[rb + 8 * 208];
                al[mt][0] = b0.x; al[mt][1] = b1.x; al[mt][2] = b0.y; al[mt][3] = b1.y;
            }
#pragma unroll
            for (int nt = 0; nt < 4; nt++) {
                int nb = (wn * 32 + nt * 8 + g) * 208 + kt * 16 + 4 * t;
                uint2 kb = *(const uint2*)&KH[nb];
                uint2 kl = *(const uint2*)&KL[nb];
                unsigned bh[2] = {kb.x, kb.y};
                unsigned bl[2] = {kl.x, kl.y};
#pragma unroll
                for (int mt = 0; mt < 2; mt++) {
                    mma16(sacc[mt][nt], ah[mt], bh);
                    mma16(sacc[mt][nt], ah[mt], bl);
                    mma16(sacc[mt][nt], al[mt], bh);
                }
            }
        }

        // ---- scale + causal mask ----
#pragma unroll
        for (int mt = 0; mt < 2; mt++)
#pragma unroll
            for (int nt = 0; nt < 4; nt++)
#pragma unroll
                for (int c = 0; c < 4; c++) {
                    int col = n0 + wn * 32 + nt * 8 + 2 * t + (c & 1);
                    int row = m0 + wm * 32 + mt * 16 + g + (c >> 1) * 8;
                    float v = sacc[mt][nt][c] * scale;
                    if (col > row) v = -1e30f;
                    sacc[mt][nt][c] = v;
                }

        // ---- online softmax ----
        float pmv[2][2], alpha_[2][2];
#pragma unroll
        for (int mt = 0; mt < 2; mt++)
#pragma unroll
            for (int hf = 0; hf < 2; hf++) {
                float pm = -1e30f;
#pragma unroll
                for (int nt = 0; nt < 4; nt++)
                    pm = fmaxf(pm, fmaxf(sacc[mt][nt][hf * 2], sacc[mt][nt][hf * 2 + 1]));
                pm = fmaxf(pm, __shfl_xor_sync(0xffffffffu, pm, 1));
                pm = fmaxf(pm, __shfl_xor_sync(0xffffffffu, pm, 2));
                pmv[mt][hf] = pm;
                if (t == 0) red[wn * 128 + wm * 32 + mt * 16 + hf * 8 + g] = pm;
            }
        __syncthreads();   // max exchange; also fences all K-frag reads before P STS
#pragma unroll
        for (int mt = 0; mt < 2; mt++)
#pragma unroll
            for (int hf = 0; hf < 2; hf++) {
                int rowl = wm * 32 + mt * 16 + hf * 8 + g;
                float comb = fmaxf(pmv[mt][hf], red[(wn ^ 1) * 128 + rowl]);
                float mnew = fmaxf(mrow[mt][hf], comb);
                alpha_[mt][hf] = __expf(mrow[mt][hf] - mnew);
                mrow[mt][hf] = mnew;
                float ps = 0.f;
#pragma unroll
                for (int nt = 0; nt < 4; nt++)
#pragma unroll
                    for (int k2 = 0; k2 < 2; k2++) {
                        int c = hf * 2 + k2;
                        float p = __expf(sacc[mt][nt][c] - mnew);
                        sacc[mt][nt][c] = p;
                        ps += p;
                    }
                lrow[mt][hf] = lrow[mt][hf] * alpha_[mt][hf] + ps;
            }
#pragma unroll
        for (int mt = 0; mt < 2; mt++)
#pragma unroll
            for (int nt = 0; nt < 8; nt++)
#pragma unroll
                for (int c = 0; c < 4; c++)
                    oacc[mt][nt][c] *= alpha_[mt][c >> 1];

        // ---- pack P (bf16 hi/lo, s-paired) into dead K area ----
        {
            unsigned* PHw = (unsigned*)KH;
            unsigned* PLw = (unsigned*)KL;
#pragma unroll
            for (int mt = 0; mt < 2; mt++)
#pragma unroll
                for (int rh = 0; rh < 2; rh++) {
                    int m = wm * 32 + mt * 16 + rh * 8 + g;
#pragma unroll
                    for (int cp = 0; cp < 2; cp++) {
                        unsigned loE, loO;
                        unsigned hiE = packsplit(sacc[mt][cp * 2][rh * 2],
                                                 sacc[mt][cp * 2][rh * 2 + 1], loE);
                        unsigned hiO = packsplit(sacc[mt][cp * 2 + 1][rh * 2],
                                                 sacc[mt][cp * 2 + 1][rh * 2 + 1], loO);
                        int w = m * 40 + (wn * 2 + cp) * 8 + 2 * t;
                        *(uint2*)&PHw[w] = make_uint2(hiE, hiO);
                        *(uint2*)&PLw[w] = make_uint2(loE, loO);
                    }
                }
        }
        __syncthreads();   // P visible to both wn warps

        // ---- O += P V : warp owns d-half (wn), full s (k=64) ----
        {
            const unsigned* PHw = (const unsigned*)KH;
            const unsigned* PLw = (const unsigned*)KL;
#pragma unroll
            for (int kt = 0; kt < 4; kt++) {
                unsigned ah[2][4], al[2][4];
#pragma unroll
                for (int mt = 0; mt < 2; mt++) {
                    int w0 = (wm * 32 + mt * 16 + g) * 40 + kt * 8 + 2 * t;
                    uint2 p0 = *(const uint2*)&PHw[w0];
                    uint2 p1 = *(const uint2*)&PHw[w0 + 320];
                    ah[mt][0] = p0.x; ah[mt][1] = p1.x; ah[mt][2] = p0.y; ah[mt][3] = p1.y;
                    uint2 q0 = *(const uint2*)&PLw[w0];
                    uint2 q1 = *(const uint2*)&PLw[w0 + 320];
                    al[mt][0] = q0.x; al[mt][1] = q1.x; al[mt][2] = q0.y; al[mt][3] = q1.y;
                }
#pragma unroll
                for (int nt = 0; nt < 8; nt++) {
                    int vb = (wn * 64 + nt * 8 + g) * 80 + kt * 16 + 4 * t;
                    uint2 vh = *(const uint2*)&VTH[vb];
                    uint2 vl = *(const uint2*)&VTL[vb];
                    unsigned bh[2] = {vh.x, vh.y};
                    unsigned bl[2] = {vl.x, vl.y};
#pragma unroll
                    for (int mt = 0; mt < 2; mt++) {
                        mma16(oacc[mt][nt], ah[mt], bh);
                        mma16(oacc[mt][nt], ah[mt], bl);
                        mma16(oacc[mt][nt], al[mt], bh);
                    }
                }
            }
        }
    }

    // ---- epilogue: exchange l across wn pair; each warp stores its d-half ----
    float lsum[2][2];
#pragma unroll
    for (int mt = 0; mt < 2; mt++)
#pragma unroll
        for (int hf = 0; hf < 2; hf++) {
            float lq = lrow[mt][hf];
            lq += __shfl_xor_sync(0xffffffffu, lq, 1);
            lq += __shfl_xor_sync(0xffffffffu, lq, 2);
            lsum[mt][hf] = lq;
        }
    __syncthreads();
    if (t == 0) {
#pragma unroll
        for (int mt = 0; mt < 2; mt++)
#pragma unroll
            for (int hf = 0; hf < 2; hf++)
                red[wn * 128 + wm * 32 + mt * 16 + hf * 8 + g] = lsum[mt][hf];
    }
    __syncthreads();
#pragma unroll
    for (int mt = 0; mt < 2; mt++)
#pragma unroll
        for (int hf = 0; hf < 2; hf++) {
            int rowl = wm * 32 + mt * 16 + hf * 8 + g;
            float ltot = lsum[mt][hf] + red[(wn ^ 1) * 128 + rowl];
            float inv = 1.f / ltot;
            int row = m0 + rowl;
#pragma unroll
            for (int nt = 0; nt < 8; nt++) {
                int col = wn * 64 + nt * 8 + 2 * t;
                float v0 = oacc[mt][nt][hf * 2]     * inv;
                float v1 = oacc[mt][nt][hf * 2 + 1] * inv;
                *(float2*)&g_AO[(size_t)row * (NH * HD) + h * HD + col] = make_float2(v0, v1);
            }
        }
}

// ---------------- launch ----------------------------------------------------
extern "C" void kernel_launch(void* const* d_in, const int* in_sizes, int n_in,
                              void* d_out, int out_size)
{
    const float* X     = (const float*)d_in[0];
    const float* W_DKV = (const float*)d_in[2];
    const float* W_UK  = (const float*)d_in[3];
    const float* W_UV  = (const float*)d_in[4];
    const float* W_DQ  = (const float*)d_in[5];
    const float* W_UQ  = (const float*)d_in[6];
    const float* W_QR  = (const float*)d_in[7];
    const float* W_KR  = (const float*)d_in[8];
    const float* W_O   = (const float*)d_in[9];
    float* out = (float*)d_out;

    float *cKV, *cQ, *qR, *kR, *Vb, *AO;
    unsigned short *QHp, *QLp, *KHp, *KLp;
    cudaGetSymbolAddress((void**)&cKV, g_cKV);
    cudaGetSymbolAddress((void**)&cQ,  g_cQ);
    cudaGetSymbolAddress((void**)&qR,  g_qR);
    cudaGetSymbolAddress((void**)&kR,  g_kR);
    cudaGetSymbolAddress((void**)&Vb,  g_Vb);
    cudaGetSymbolAddress((void**)&AO,  g_AO);
    cudaGetSymbolAddress((void**)&QHp, g_QH);
    cudaGetSymbolAddress((void**)&QLp, g_QL);
    cudaGetSymbolAddress((void**)&KHp, g_KH);
    cudaGetSymbolAddress((void**)&KLp, g_KL);

    dim3 blk(256);

    // P1: X @ {W_DQ, W_DKV, W_KR}
    {
        GroupArgs ga = {};
        ga.A[0] = X;  ga.B[0] = W_DQ;  ga.C[0] = cQ;  ga.K[0] = HID_D; ga.N[0] = CQ;   ga.mode[0] = 0;
        ga.A[1] = X;  ga.B[1] = W_DKV; ga.C[1] = cKV; ga.K[1] = HID_D; ga.N[1] = CKV;  ga.mode[1] = 0;
        ga.A[2] = X;  ga.B[2] = W_KR;  ga.C[2] = kR;  ga.K[2] = HID_D; ga.N[2] = DR;   ga.mode[2] = 0;
        ga.tstart[0] = 0; ga.tstart[1] = 12; ga.tstart[2] = 16; ga.tstart[3] = 17; ga.tstart[4] = 17;
        mma_gemm_grouped<<<dim3(16, 17), blk>>>(ga);
    }
    // P2: {UQ->bf16 Q, QR->qR, UK->bf16 K, UV->V f32}
    {
        GroupArgs ga = {};
        ga.A[0] = cQ;  ga.B[0] = W_UQ; ga.C[0] = QHp; ga.Clo[0] = QLp; ga.K[0] = CQ;  ga.N[0] = NH * HD; ga.mode[0] = 1;
        ga.A[1] = cQ;  ga.B[1] = W_QR; ga.C[1] = qR;                   ga.K[1] = CQ;  ga.N[1] = NH * DR; ga.mode[1] = 0;
        ga.A[2] = cKV; ga.B[2] = W_UK; ga.C[2] = KHp; ga.Clo[2] = KLp; ga.K[2] = CKV; ga.N[2] = NH * HD; ga.mode[2] = 1;
        ga.A[3] = cKV; ga.B[3] = W_UV; ga.C[3] = Vb;                   ga.K[3] = CKV; ga.N[3] = NH * HD; ga.mode[3] = 2;
        ga.tstart[0] = 0; ga.tstart[1] = 16; ga.tstart[2] = 24; ga.tstart[3] = 40; ga.tstart[4] = 56;
        mma_gemm_grouped<<<dim3(16, 56), blk>>>(ga);
    }

    // fused prep (3rd launch)
    prep_kernel<<<5376, 256>>>();

    // attention (4th launch -> profiled)
    cudaFuncSetAttribute(attn_mma_kernel, cudaFuncAttributeMaxDynamicSharedMemorySize, ATTN_SMEM);
    attn_mma_kernel<<<256, 256, ATTN_SMEM>>>();

    // out = AO @ W_O
    {
        GroupArgs ga = {};
        ga.A[0] = AO; ga.B[0] = W_O; ga.C[0] = out; ga.K[0] = NH * HD; ga.N[0] = HID_D; ga.mode[0] = 0;
        ga.tstart[0] = 0; ga.tstart[1] = 16; ga.tstart[2] = 16; ga.tstart[3] = 16; ga.tstart[4] = 16;
        mma_gemm_grouped<<<dim3(16, 16), blk>>>(ga);
    }
}

// round 8
// speedup vs baseline: 1.0242x; 1.0242x over previous
#include <cuda_runtime.h>
#include <cuda_bf16.h>
#include <math.h>

#define S_LEN 2048
#define HID_D 2048
#define NH 16
#define HD 128
#define DR 64
#define DQK 192
#define CKV 512
#define CQ 1536

// ---------------- scratch ----------------------------------------------------
__device__ float g_cKV[S_LEN * CKV];
__device__ float g_cQ [S_LEN * CQ];
__device__ float g_qR [S_LEN * NH * DR];
__device__ float g_kR [S_LEN * DR];
__device__ float g_Vb [NH * S_LEN * HD];      // [h][s][128] f32
__device__ float g_AO [S_LEN * NH * HD];      // [s][h*128+d]
__device__ unsigned short g_QH[NH * S_LEN * DQK];   // k-paired bf16 hi
__device__ unsigned short g_QL[NH * S_LEN * DQK];
__device__ unsigned short g_KH[NH * S_LEN * DQK];
__device__ unsigned short g_KL[NH * S_LEN * DQK];
__device__ unsigned short g_VTH[NH * HD * S_LEN];   // [h][d][s] s-paired
__device__ unsigned short g_VTL[NH * HD * S_LEN];

// pair-permutation within a 16-chunk: (2t,2t+1)->(4t,4t+1), (2t+8,2t+9)->(4t+2,4t+3)
__device__ __forceinline__ int pi16(int c) {
    return (c & 1) + (((c & 7) >> 1) << 2) + ((c >> 3) << 1);
}
__device__ __forceinline__ int pi16e(int c) {
    return (((c & 7) >> 1) << 2) + ((c >> 3) << 1);
}

// ---------------- tf32 helpers ---------------------------------------------
__device__ __forceinline__ unsigned f2tf(float x) {
    unsigned u;
    asm("cvt.rna.tf32.f32 %0, %1;" : "=r"(u) : "f"(x));
    return u;
}

__device__ __forceinline__ void mma8(float c[4], const unsigned a[4], const unsigned b[2]) {
    asm volatile(
        "mma.sync.aligned.m16n8k8.row.col.f32.tf32.tf32.f32 "
        "{%0,%1,%2,%3}, {%4,%5,%6,%7}, {%8,%9}, {%0,%1,%2,%3};\n"
        : "+f"(c[0]), "+f"(c[1]), "+f"(c[2]), "+f"(c[3])
        : "r"(a[0]), "r"(a[1]), "r"(a[2]), "r"(a[3]), "r"(b[0]), "r"(b[1]));
}

// ---------------- bf16 helpers ----------------------------------------------
__device__ __forceinline__ void mma16(float c[4], const unsigned a[4], const unsigned b[2]) {
    asm volatile(
        "mma.sync.aligned.m16n8k16.row.col.f32.bf16.bf16.f32 "
        "{%0,%1,%2,%3}, {%4,%5,%6,%7}, {%8,%9}, {%0,%1,%2,%3};\n"
        : "+f"(c[0]), "+f"(c[1]), "+f"(c[2]), "+f"(c[3])
        : "r"(a[0]), "r"(a[1]), "r"(a[2]), "r"(a[3]), "r"(b[0]), "r"(b[1]));
}

__device__ __forceinline__ void split2(float x, unsigned short &hh, unsigned short &ll) {
    __nv_bfloat16 bh = __float2bfloat16(x);
    float hf = __bfloat162float(bh);
    __nv_bfloat16 bl = __float2bfloat16(x - hf);
    hh = __bfloat16_as_ushort(bh);
    ll = __bfloat16_as_ushort(bl);
}

__device__ __forceinline__ unsigned bfbits(float x) {
    return (unsigned)__bfloat16_as_ushort(__float2bfloat16(x));
}
__device__ __forceinline__ float bfval(float x) {
    return __bfloat162float(__float2bfloat16(x));
}
__device__ __forceinline__ unsigned packsplit(float x, float y, unsigned &lo) {
    float xh = bfval(x), yh = bfval(y);
    unsigned hi = bfbits(x) | (bfbits(y) << 16);
    lo = bfbits(x - xh) | (bfbits(y - yh) << 16);
    return hi;
}

// ---------------- grouped tf32 tensor-core GEMM -----------------------------
struct GroupArgs {
    const float* A[4];
    const float* B[4];
    void*        C[4];
    void*        Clo[4];
    int K[4];
    int N[4];
    int mode[4];
    int tstart[5];
};

__global__ __launch_bounds__(256, 2)
void mma_gemm_grouped(GroupArgs ga)
{
    __shared__ unsigned As[2][128][20];
    __shared__ unsigned Bs[2][16][136];

    int g = 0;
    while (blockIdx.y >= (unsigned)ga.tstart[g + 1]) g++;
    const float* __restrict__ A = ga.A[g];
    const float* __restrict__ B = ga.B[g];
    const int K = ga.K[g];
    const int N = ga.N[g];
    const int mode = ga.mode[g];

    const int tid  = threadIdx.x;
    const int lane = tid & 31;
    const int warp = tid >> 5;
    const int wm   = warp & 1;
    const int wn   = warp >> 1;
    const int m0   = blockIdx.x * 128;
    const int n0   = (blockIdx.y - ga.tstart[g]) * 128;
    const int fr   = lane >> 2;
    const int fc   = lane & 3;

    float acc[4][4][4];
#pragma unroll
    for (int mt = 0; mt < 4; mt++)
#pragma unroll
        for (int nt = 0; nt < 4; nt++)
#pragma unroll
            for (int i = 0; i < 4; i++) acc[mt][nt][i] = 0.f;

    float4 ra[2], rb[2];

    const int rowA0 = (tid + 0)   >> 2;   const int kcA0 = ((tid + 0)   & 3) * 4;
    const int rowA1 = (tid + 256) >> 2;   const int kcA1 = ((tid + 256) & 3) * 4;
    const int kkB0  = (tid + 0)   >> 5;   const int c4B0 = ((tid + 0)   & 31) * 4;
    const int kkB1  = (tid + 256) >> 5;   const int c4B1 = ((tid + 256) & 31) * 4;

#define LDG_TILE(k0)                                                            \
    {                                                                           \
        ra[0] = *(const float4*)&A[(size_t)(m0 + rowA0) * K + (k0) + kcA0];     \
        ra[1] = *(const float4*)&A[(size_t)(m0 + rowA1) * K + (k0) + kcA1];     \
        if (n0 + c4B0 < N)                                                      \
            rb[0] = *(const float4*)&B[(size_t)((k0) + kkB0) * N + n0 + c4B0];  \
        else rb[0] = make_float4(0.f, 0.f, 0.f, 0.f);                           \
        if (n0 + c4B1 < N)                                                      \
            rb[1] = *(const float4*)&B[(size_t)((k0) + kkB1) * N + n0 + c4B1];  \
        else rb[1] = make_float4(0.f, 0.f, 0.f, 0.f);                           \
    }

#define STS_TILE(buf)                                                           \
    {                                                                           \
        uint4 ua0 = make_uint4(f2tf(ra[0].x), f2tf(ra[0].y), f2tf(ra[0].z), f2tf(ra[0].w)); \
        uint4 ua1 = make_uint4(f2tf(ra[1].x), f2tf(ra[1].y), f2tf(ra[1].z), f2tf(ra[1].w)); \
        *(uint4*)&As[buf][rowA0][kcA0] = ua0;                                   \
        *(uint4*)&As[buf][rowA1][kcA1] = ua1;                                   \
        uint4 ub0 = make_uint4(f2tf(rb[0].x), f2tf(rb[0].y), f2tf(rb[0].z), f2tf(rb[0].w)); \
        uint4 ub1 = make_uint4(f2tf(rb[1].x), f2tf(rb[1].y), f2tf(rb[1].z), f2tf(rb[1].w)); \
        *(uint4*)&Bs[buf][kkB0][c4B0] = ub0;                                    \
        *(uint4*)&Bs[buf][kkB1][c4B1] = ub1;                                    \
    }

#define COMPUTE(buf)                                                            \
    {                                                                           \
        _Pragma("unroll")                                                       \
        for (int ks = 0; ks < 2; ks++) {                                        \
            unsigned af[4][4], bf[4][2];                                        \
            _Pragma("unroll")                                                   \
            for (int mt = 0; mt < 4; mt++) {                                    \
                int mr = wm * 64 + mt * 16 + fr;                                \
                af[mt][0] = As[buf][mr    ][ks * 8 + fc];                       \
                af[mt][1] = As[buf][mr + 8][ks * 8 + fc];                       \
                af[mt][2] = As[buf][mr    ][ks * 8 + fc + 4];                   \
                af[mt][3] = As[buf][mr + 8][ks * 8 + fc + 4];                   \
            }                                                                   \
            _Pragma("unroll")                                                   \
            for (int nt = 0; nt < 4; nt++) {                                    \
                int nc = wn * 32 + nt * 8 + fr;                                 \
                bf[nt][0] = Bs[buf][ks * 8 + fc    ][nc];                       \
                bf[nt][1] = Bs[buf][ks * 8 + fc + 4][nc];                       \
            }                                                                   \
            _Pragma("unroll")                                                   \
            for (int mt = 0; mt < 4; mt++)                                      \
                _Pragma("unroll")                                               \
                for (int nt = 0; nt < 4; nt++)                                  \
                    mma8(acc[mt][nt], af[mt], bf[nt]);                          \
        }                                                                       \
    }

    LDG_TILE(0);
    STS_TILE(0);
    __syncthreads();

    int buf = 0;
#pragma unroll 1
    for (int k0 = 16; k0 < K; k0 += 16) {
        LDG_TILE(k0);
        COMPUTE(buf);
        STS_TILE(buf ^ 1);
        __syncthreads();
        buf ^= 1;
    }
    COMPUTE(buf);

#pragma unroll
    for (int mt = 0; mt < 4; mt++) {
#pragma unroll
        for (int nt = 0; nt < 4; nt++) {
            int row = m0 + wm * 64 + mt * 16 + fr;
            int col = n0 + wn * 32 + nt * 8 + fc * 2;
            if (mode == 0) {
                float* Cf = (float*)ga.C[g];
                if (col < N) {
                    *(float2*)&Cf[(size_t)row * N + col] =
                        make_float2(acc[mt][nt][0], acc[mt][nt][1]);
                    *(float2*)&Cf[(size_t)(row + 8) * N + col] =
                        make_float2(acc[mt][nt][2], acc[mt][nt][3]);
                }
            } else if (mode == 1) {
                unsigned short* CH = (unsigned short*)ga.C[g];
                unsigned short* CL = (unsigned short*)ga.Clo[g];
                int hh = col >> 7, d = col & 127;
                int dp = (d & ~15) | pi16e(d & 15);
                size_t b0 = ((size_t)(hh * S_LEN + row)) * DQK + dp;
                size_t b1 = ((size_t)(hh * S_LEN + row + 8)) * DQK + dp;
                unsigned lo, hi;
                hi = packsplit(acc[mt][nt][0], acc[mt][nt][1], lo);
                *(unsigned*)&CH[b0] = hi; *(unsigned*)&CL[b0] = lo;
                hi = packsplit(acc[mt][nt][2], acc[mt][nt][3], lo);
                *(unsigned*)&CH[b1] = hi; *(unsigned*)&CL[b1] = lo;
            } else {
                float* Cf = (float*)ga.C[g];
                int hh = col >> 7, d = col & 127;
                *(float2*)&Cf[(size_t)((hh * S_LEN) + row)     * HD + d] =
                    make_float2(acc[mt][nt][0], acc[mt][nt][1]);
                *(float2*)&Cf[(size_t)((hh * S_LEN) + row + 8) * HD + d] =
                    make_float2(acc[mt][nt][2], acc[mt][nt][3]);
            }
        }
    }
#undef LDG_TILE
#undef STS_TILE
#undef COMPUTE
}

// ---------------- separate prep kernels (R5 structure, pi16 bodies) ----------
__global__ void rope_q_kernel()
{
    int idx = blockIdx.x * blockDim.x + threadIdx.x;
    if (idx >= S_LEN * NH * 32) return;
    int i = idx & 31;
    int h = (idx >> 5) & 15;
    int t = idx >> 9;
    float invf = powf(10000.0f, -(2.0f * i) / 64.0f);
    float ang = (float)t * invf;
    float s, c;
    sincosf(ang, &s, &c);
    const float* x = g_qR + (size_t)t * (NH * DR) + h * DR;
    float x1 = x[i], x2 = x[i + 32];
    float r1 = x1 * c - x2 * s;
    float r2 = x2 * c + x1 * s;
    size_t base = ((size_t)(h * S_LEN + t)) * DQK;
    int d1 = 128 + i, d2 = 160 + i;
    int d1p = (d1 & ~15) | pi16(d1 & 15);
    int d2p = (d2 & ~15) | pi16(d2 & 15);
    unsigned short hh, ll;
    split2(r1, hh, ll); g_QH[base + d1p] = hh; g_QL[base + d1p] = ll;
    split2(r2, hh, ll); g_QH[base + d2p] = hh; g_QL[base + d2p] = ll;
}

__global__ void rope_k_kernel()
{
    int idx = blockIdx.x * blockDim.x + threadIdx.x;
    if (idx >= S_LEN * 32) return;
    int i = idx & 31;
    int t = idx >> 5;
    float invf = powf(10000.0f, -(2.0f * i) / 64.0f);
    float ang = (float)t * invf;
    float s, c;
    sincosf(ang, &s, &c);
    const float* x = g_kR + (size_t)t * DR;
    float r1 = x[i] * c - x[i + 32] * s;
    float r2 = x[i + 32] * c + x[i] * s;
    unsigned short h1, l1, h2, l2;
    split2(r1, h1, l1);
    split2(r2, h2, l2);
    int d1 = 128 + i, d2 = 160 + i;
    int d1p = (d1 & ~15) | pi16(d1 & 15);
    int d2p = (d2 & ~15) | pi16(d2 & 15);
#pragma unroll
    for (int h = 0; h < NH; h++) {
        size_t base = ((size_t)(h * S_LEN + t)) * DQK;
        g_KH[base + d1p] = h1; g_KL[base + d1p] = l1;
        g_KH[base + d2p] = h2; g_KL[base + d2p] = l2;
    }
}

__global__ __launch_bounds__(256)
void vtrans_kernel()
{
    __shared__ float sv[64][133];
    const int h  = blockIdx.y;
    const int s0 = blockIdx.x * 64;
    const int tid = threadIdx.x;
    const float* src = g_Vb + ((size_t)h * S_LEN + s0) * HD;
#pragma unroll
    for (int i = 0; i < 8; i++) {
        int idx = tid + i * 256;
        int r = idx >> 5, c4 = (idx & 31) * 4;
        float4 v = *(const float4*)&src[r * HD + c4];
        sv[r][c4] = v.x; sv[r][c4 + 1] = v.y; sv[r][c4 + 2] = v.z; sv[r][c4 + 3] = v.w;
    }
    __syncthreads();
    int sl = tid & 63, d0 = tid >> 6;
    int sp = s0 + ((sl & ~15) | pi16(sl & 15));
#pragma unroll
    for (int dd = 0; dd < 32; dd++) {
        int d = d0 * 32 + dd;
        unsigned short hh, ll;
        split2(sv[sl][d], hh, ll);
        size_t o = ((size_t)(h * HD + d)) * S_LEN + sp;
        g_VTH[o] = hh;
        g_VTL[o] = ll;
    }
}

// ---------------- bf16x3 tensor-core flash attention (R6 version) ------------
// smem: QH[128][208]@0, QL@53248, KH[64][208]@106496, KL@133120,
//       VTH[128][80]@159744, VTL@180224, red@200704
#define ATTN_SMEM 201728

__global__ __launch_bounds__(256, 1)
void attn_mma_kernel()
{
    extern __shared__ char smraw[];
    unsigned short* QH  = (unsigned short*)(smraw);
    unsigned short* QL  = (unsigned short*)(smraw + 53248);
    unsigned short* KH  = (unsigned short*)(smraw + 106496);
    unsigned short* KL  = (unsigned short*)(smraw + 133120);
    unsigned short* VTH = (unsigned short*)(smraw + 159744);
    unsigned short* VTL = (unsigned short*)(smraw + 180224);
    float* red = (float*)(smraw + 200704);

    const int bid  = blockIdx.x;
    const int mb   = 15 - (bid >> 4);
    const int h    = bid & 15;
    const int m0   = mb * 128;
    const int tid  = threadIdx.x;
    const int lane = tid & 31;
    const int warp = tid >> 5;
    const int wm = warp >> 1, wn = warp & 1;
    const int g = lane >> 2, t = lane & 3;

    // stage Q
    {
        const uint4* sH = (const uint4*)(g_QH + ((size_t)h * S_LEN + m0) * DQK);
        const uint4* sL = (const uint4*)(g_QL + ((size_t)h * S_LEN + m0) * DQK);
        uint4* dH = (uint4*)QH;
        uint4* dL = (uint4*)QL;
#pragma unroll
        for (int i = 0; i < 12; i++) {
            int idx = tid + i * 256;
            int r = idx / 24, u = idx - r * 24;
            dH[r * 26 + u] = sH[idx];
            dL[r * 26 + u] = sL[idx];
        }
    }

    float oacc[2][16][4];
#pragma unroll
    for (int mt = 0; mt < 2; mt++)
#pragma unroll
        for (int nt = 0; nt < 16; nt++)
#pragma unroll
            for (int c = 0; c < 4; c++) oacc[mt][nt][c] = 0.f;

    float mrow[2][2] = {{-1e30f, -1e30f}, {-1e30f, -1e30f}};
    float lrow[2][2] = {{0.f, 0.f}, {0.f, 0.f}};

    const float scale = 0.07216878364870322f;
    const int ntiles = 2 * mb + 2;

    const uint4* KHg = (const uint4*)(g_KH + (size_t)h * S_LEN * DQK);
    const uint4* KLg = (const uint4*)(g_KL + (size_t)h * S_LEN * DQK);
    const uint4* VHg = (const uint4*)(g_VTH + (size_t)h * HD * S_LEN);
    const uint4* VLg = (const uint4*)(g_VTL + (size_t)h * HD * S_LEN);
    uint4* KH4 = (uint4*)KH;
    uint4* KL4 = (uint4*)KL;
    uint4* VH4 = (uint4*)VTH;
    uint4* VL4 = (uint4*)VTL;

#pragma unroll 1
    for (int tile = 0; tile < ntiles; tile++) {
        const int n0 = tile * 64;
        __syncthreads();

        {
            const uint4* sH = KHg + (size_t)n0 * 24;
            const uint4* sL = KLg + (size_t)n0 * 24;
#pragma unroll
            for (int i = 0; i < 6; i++) {
                int idx = tid + i * 256;
                int r = idx / 24, u = idx - r * 24;
                KH4[r * 26 + u] = sH[idx];
                KL4[r * 26 + u] = sL[idx];
            }
        }
        {
            const uint4* sH = VHg + (n0 >> 3);
            const uint4* sL = VLg + (n0 >> 3);
#pragma unroll
            for (int i = 0; i < 4; i++) {
                int idx = tid + i * 256;
                int d = idx >> 3, u = idx & 7;
                VH4[d * 10 + u] = sH[d * 256 + u];
                VL4[d * 10 + u] = sL[d * 256 + u];
            }
        }
        __syncthreads();

        // ---- S = Q K^T (paired LDS.64 frag loads) ----
        float sacc[2][4][4];
#pragma unroll
        for (int mt = 0; mt < 2; mt++)
#pragma unroll
            for (int nt = 0; nt < 4; nt++)
#pragma unroll
                for (int c = 0; c < 4; c++) sacc[mt][nt][c] = 0.f;

#pragma unroll
        for (int kt = 0; kt < 12; kt++) {
            unsigned ah[2][4], al[2][4];
#pragma unroll
            for (int mt = 0; mt < 2; mt++) {
                int rb = (wm * 32 + mt * 16 + g) * 208 + kt * 16 + 4 * t;
                uint2 a0 = *(const uint2*)&QH[rb];
                uint2 a1 = *(const uint2*)&QH[rb + 8 * 208];
                ah[mt][0] = a0.x; ah[mt][1] = a1.x; ah[mt][2] = a0.y; ah[mt][3] = a1.y;
                uint2 b0 = *(const uint2*)&QL[rb];
                uint2 b1 = *(const uint2*)&QL[rb + 8 * 208];
                al[mt][0] = b0.x; al[mt][1] = b1.x; al[mt][2] = b0.y; al[mt][3] = b1.y;
            }
#pragma unroll
            for (int nt = 0; nt < 4; nt++) {
                int nb = (wn * 32 + nt * 8 + g) * 208 + kt * 16 + 4 * t;
                uint2 kb = *(const uint2*)&KH[nb];
                uint2 kl = *(const uint2*)&KL[nb];
                unsigned bh[2] = {kb.x, kb.y};
                unsigned bl[2] = {kl.x, kl.y};
#pragma unroll
                for (int mt = 0; mt < 2; mt++) {
                    mma16(sacc[mt][nt], ah[mt], bh);
                    mma16(sacc[mt][nt], ah[mt], bl);
                    mma16(sacc[mt][nt], al[mt], bh);
                }
            }
        }

        // ---- scale + causal mask ----
#pragma unroll
        for (int mt = 0; mt < 2; mt++)
#pragma unroll
            for (int nt = 0; nt < 4; nt++)
#pragma unroll
                for (int c = 0; c < 4; c++) {
                    int col = n0 + wn * 32 + nt * 8 + 2 * t + (c & 1);
                    int row = m0 + wm * 32 + mt * 16 + g + (c >> 1) * 8;
                    float v = sacc[mt][nt][c] * scale;
                    if (col > row) v = -1e30f;
                    sacc[mt][nt][c] = v;
                }

        // ---- online softmax ----
        float pmv[2][2], alpha_[2][2];
#pragma unroll
        for (int mt = 0; mt < 2; mt++)
#pragma unroll
            for (int hf = 0; hf < 2; hf++) {
                float pm = -1e30f;
#pragma unroll
                for (int nt = 0; nt < 4; nt++)
                    pm = fmaxf(pm, fmaxf(sacc[mt][nt][hf * 2], sacc[mt][nt][hf * 2 + 1]));
                pm = fmaxf(pm, __shfl_xor_sync(0xffffffffu, pm, 1));
                pm = fmaxf(pm, __shfl_xor_sync(0xffffffffu, pm, 2));
                pmv[mt][hf] = pm;
                if (t == 0) red[wn * 128 + wm * 32 + mt * 16 + hf * 8 + g] = pm;
            }
        __syncthreads();
#pragma unroll
        for (int mt = 0; mt < 2; mt++)
#pragma unroll
            for (int hf = 0; hf < 2; hf++) {
                int rowl = wm * 32 + mt * 16 + hf * 8 + g;
                float comb = fmaxf(pmv[mt][hf], red[(wn ^ 1) * 128 + rowl]);
                float mnew = fmaxf(mrow[mt][hf], comb);
                alpha_[mt][hf] = __expf(mrow[mt][hf] - mnew);
                mrow[mt][hf] = mnew;
                float ps = 0.f;
#pragma unroll
                for (int nt = 0; nt < 4; nt++)
#pragma unroll
                    for (int k2 = 0; k2 < 2; k2++) {
                        int c = hf * 2 + k2;
                        float p = __expf(sacc[mt][nt][c] - mnew);
                        sacc[mt][nt][c] = p;
                        ps += p;
                    }
                lrow[mt][hf] = lrow[mt][hf] * alpha_[mt][hf] + ps;
            }
#pragma unroll
        for (int mt = 0; mt < 2; mt++)
#pragma unroll
            for (int nt = 0; nt < 16; nt++)
#pragma unroll
                for (int c = 0; c < 4; c++)
                    oacc[mt][nt][c] *= alpha_[mt][c >> 1];

        // ---- O += P V (register P, paired LDS.64 V loads) ----
#pragma unroll
        for (int kt2 = 0; kt2 < 2; kt2++) {
            unsigned aph[2][4], apl[2][4];
#pragma unroll
            for (int mt = 0; mt < 2; mt++) {
                aph[mt][0] = packsplit(sacc[mt][2 * kt2][0],     sacc[mt][2 * kt2][1],     apl[mt][0]);
                aph[mt][1] = packsplit(sacc[mt][2 * kt2][2],     sacc[mt][2 * kt2][3],     apl[mt][1]);
                aph[mt][2] = packsplit(sacc[mt][2 * kt2 + 1][0], sacc[mt][2 * kt2 + 1][1], apl[mt][2]);
                aph[mt][3] = packsplit(sacc[mt][2 * kt2 + 1][2], sacc[mt][2 * kt2 + 1][3], apl[mt][3]);
            }
#pragma unroll
            for (int nt = 0; nt < 16; nt++) {
                int vb = (nt * 8 + g) * 80 + wn * 32 + kt2 * 16 + 4 * t;
                uint2 vh = *(const uint2*)&VTH[vb];
                uint2 vl = *(const uint2*)&VTL[vb];
                unsigned bh[2] = {vh.x, vh.y};
                unsigned bl[2] = {vl.x, vl.y};
#pragma unroll
                for (int mt = 0; mt < 2; mt++) {
                    mma16(oacc[mt][nt], aph[mt], bh);
                    mma16(oacc[mt][nt], aph[mt], bl);
                    mma16(oacc[mt][nt], apl[mt], bh);
                }
            }
        }
    }

    // ---- epilogue ----
    float lsum[2][2];
#pragma unroll
    for (int mt = 0; mt < 2; mt++)
#pragma unroll
        for (int hf = 0; hf < 2; hf++) {
            float lq = lrow[mt][hf];
            lq += __shfl_xor_sync(0xffffffffu, lq, 1);
            lq += __shfl_xor_sync(0xffffffffu, lq, 2);
            lsum[mt][hf] = lq;
        }

    __syncthreads();
    float* osm = (float*)smraw + wm * (32 * 132);
    if (wn == 1) {
#pragma unroll
        for (int mt = 0; mt < 2; mt++)
#pragma unroll
            for (int nt = 0; nt < 16; nt++)
#pragma unroll
                for (int c = 0; c < 4; c++) {
                    int rowl = mt * 16 + (c >> 1) * 8 + g;
                    int col = nt * 8 + 2 * t + (c & 1);
                    osm[rowl * 132 + col] = oacc[mt][nt][c];
                }
#pragma unroll
        for (int mt = 0; mt < 2; mt++)
#pragma unroll
            for (int hf = 0; hf < 2; hf++)
                if (t == 0) red[wm * 32 + mt * 16 + hf * 8 + g] = lsum[mt][hf];
    }
    __syncthreads();
    if (wn == 0) {
#pragma unroll
        for (int mt = 0; mt < 2; mt++)
#pragma unroll
            for (int hf = 0; hf < 2; hf++) {
                int rowl = mt * 16 + hf * 8 + g;
                float ltot = lsum[mt][hf] + red[wm * 32 + rowl];
                float inv = 1.f / ltot;
                int row = m0 + wm * 32 + rowl;
#pragma unroll
                for (int nt = 0; nt < 16; nt++) {
                    int col = nt * 8 + 2 * t;
                    float v0 = (oacc[mt][nt][hf * 2]     + osm[rowl * 132 + col])     * inv;
                    float v1 = (oacc[mt][nt][hf * 2 + 1] + osm[rowl * 132 + col + 1]) * inv;
                    *(float2*)&g_AO[(size_t)row * (NH * HD) + h * HD + col] = make_float2(v0, v1);
                }
            }
    }
}

// ---------------- launch ----------------------------------------------------
extern "C" void kernel_launch(void* const* d_in, const int* in_sizes, int n_in,
                              void* d_out, int out_size)
{
    const float* X     = (const float*)d_in[0];
    const float* W_DKV = (const float*)d_in[2];
    const float* W_UK  = (const float*)d_in[3];
    const float* W_UV  = (const float*)d_in[4];
    const float* W_DQ  = (const float*)d_in[5];
    const float* W_UQ  = (const float*)d_in[6];
    const float* W_QR  = (const float*)d_in[7];
    const float* W_KR  = (const float*)d_in[8];
    const float* W_O   = (const float*)d_in[9];
    float* out = (float*)d_out;

    float *cKV, *cQ, *qR, *kR, *Vb, *AO;
    unsigned short *QHp, *QLp, *KHp, *KLp;
    cudaGetSymbolAddress((void**)&cKV, g_cKV);
    cudaGetSymbolAddress((void**)&cQ,  g_cQ);
    cudaGetSymbolAddress((void**)&qR,  g_qR);
    cudaGetSymbolAddress((void**)&kR,  g_kR);
    cudaGetSymbolAddress((void**)&Vb,  g_Vb);
    cudaGetSymbolAddress((void**)&AO,  g_AO);
    cudaGetSymbolAddress((void**)&QHp, g_QH);
    cudaGetSymbolAddress((void**)&QLp, g_QL);
    cudaGetSymbolAddress((void**)&KHp, g_KH);
    cudaGetSymbolAddress((void**)&KLp, g_KL);

    dim3 blk(256);

    // P1: X @ {W_DQ, W_DKV, W_KR}
    {
        GroupArgs ga = {};
        ga.A[0] = X;  ga.B[0] = W_DQ;  ga.C[0] = cQ;  ga.K[0] = HID_D; ga.N[0] = CQ;   ga.mode[0] = 0;
        ga.A[1] = X;  ga.B[1] = W_DKV; ga.C[1] = cKV; ga.K[1] = HID_D; ga.N[1] = CKV;  ga.mode[1] = 0;
        ga.A[2] = X;  ga.B[2] = W_KR;  ga.C[2] = kR;  ga.K[2] = HID_D; ga.N[2] = DR;   ga.mode[2] = 0;
        ga.tstart[0] = 0; ga.tstart[1] = 12; ga.tstart[2] = 16; ga.tstart[3] = 17; ga.tstart[4] = 17;
        mma_gemm_grouped<<<dim3(16, 17), blk>>>(ga);
    }
    // P2: {UQ->bf16 Q, QR->qR, UK->bf16 K, UV->V f32}
    {
        GroupArgs ga = {};
        ga.A[0] = cQ;  ga.B[0] = W_UQ; ga.C[0] = QHp; ga.Clo[0] = QLp; ga.K[0] = CQ;  ga.N[0] = NH * HD; ga.mode[0] = 1;
        ga.A[1] = cQ;  ga.B[1] = W_QR; ga.C[1] = qR;                   ga.K[1] = CQ;  ga.N[1] = NH * DR; ga.mode[1] = 0;
        ga.A[2] = cKV; ga.B[2] = W_UK; ga.C[2] = KHp; ga.Clo[2] = KLp; ga.K[2] = CKV; ga.N[2] = NH * HD; ga.mode[2] = 1;
        ga.A[3] = cKV; ga.B[3] = W_UV; ga.C[3] = Vb;                   ga.K[3] = CKV; ga.N[3] = NH * HD; ga.mode[3] = 2;
        ga.tstart[0] = 0; ga.tstart[1] = 16; ga.tstart[2] = 24; ga.tstart[3] = 40; ga.tstart[4] = 56;
        mma_gemm_grouped<<<dim3(16, 56), blk>>>(ga);
    }

    // separate prep kernels (R5 structure)
    rope_q_kernel<<<(S_LEN * NH * 32) / 256, 256>>>();
    rope_k_kernel<<<(S_LEN * 32) / 256, 256>>>();
    vtrans_kernel<<<dim3(S_LEN / 64, NH), 256>>>();

    // attention (R6 kernel)
    cudaFuncSetAttribute(attn_mma_kernel, cudaFuncAttributeMaxDynamicSharedMemorySize, ATTN_SMEM);
    attn_mma_kernel<<<256, 256, ATTN_SMEM>>>();

    // out = AO @ W_O
    {
        GroupArgs ga = {};
        ga.A[0] = AO; ga.B[0] = W_O; ga.C[0] = out; ga.K[0] = NH * HD; ga.N[0] = HID_D; ga.mode[0] = 0;
        ga.tstart[0] = 0; ga.tstart[1] = 16; ga.tstart[2] = 16; ga.tstart[3] = 16; ga.tstart[4] = 16;
        mma_gemm_grouped<<<dim3(16, 16), blk>>>(ga);
    }
}

// round 9
// speedup vs baseline: 1.0470x; 1.0222x over previous
#include <cuda_runtime.h>
#include <cuda_bf16.h>
#include <math.h>

#define S_LEN 2048
#define HID_D 2048
#define NH 16
#define HD 128
#define DR 64
#define DQK 192
#define CKV 512
#define CQ 1536

// ---------------- scratch ----------------------------------------------------
__device__ float g_cKV[S_LEN * CKV];
__device__ float g_cQ [S_LEN * CQ];
__device__ float g_qR [S_LEN * NH * DR];
__device__ float g_kR [S_LEN * DR];
__device__ float g_Vb [NH * S_LEN * HD];      // [h][s][128] f32
__device__ float g_AO [S_LEN * NH * HD];      // [s][h*128+d]
__device__ unsigned short g_QH[NH * S_LEN * DQK];   // k-paired bf16 hi
__device__ unsigned short g_QL[NH * S_LEN * DQK];
__device__ unsigned short g_KH[NH * S_LEN * DQK];
__device__ unsigned short g_KL[NH * S_LEN * DQK];
__device__ unsigned short g_VTH[NH * HD * S_LEN];   // [h][d][s] s-paired
__device__ unsigned short g_VTL[NH * HD * S_LEN];

// pair-permutation within a 16-chunk
__device__ __forceinline__ int pi16(int c) {
    return (c & 1) + (((c & 7) >> 1) << 2) + ((c >> 3) << 1);
}
__device__ __forceinline__ int pi16e(int c) {
    return (((c & 7) >> 1) << 2) + ((c >> 3) << 1);
}

// ---------------- tf32 helpers ---------------------------------------------
__device__ __forceinline__ unsigned f2tf(float x) {
    unsigned u;
    asm("cvt.rna.tf32.f32 %0, %1;" : "=r"(u) : "f"(x));
    return u;
}

__device__ __forceinline__ void mma8(float c[4], const unsigned a[4], const unsigned b[2]) {
    asm volatile(
        "mma.sync.aligned.m16n8k8.row.col.f32.tf32.tf32.f32 "
        "{%0,%1,%2,%3}, {%4,%5,%6,%7}, {%8,%9}, {%0,%1,%2,%3};\n"
        : "+f"(c[0]), "+f"(c[1]), "+f"(c[2]), "+f"(c[3])
        : "r"(a[0]), "r"(a[1]), "r"(a[2]), "r"(a[3]), "r"(b[0]), "r"(b[1]));
}

// ---------------- bf16 helpers ----------------------------------------------
__device__ __forceinline__ void mma16(float c[4], const unsigned a[4], const unsigned b[2]) {
    asm volatile(
        "mma.sync.aligned.m16n8k16.row.col.f32.bf16.bf16.f32 "
        "{%0,%1,%2,%3}, {%4,%5,%6,%7}, {%8,%9}, {%0,%1,%2,%3};\n"
        : "+f"(c[0]), "+f"(c[1]), "+f"(c[2]), "+f"(c[3])
        : "r"(a[0]), "r"(a[1]), "r"(a[2]), "r"(a[3]), "r"(b[0]), "r"(b[1]));
}

__device__ __forceinline__ void split2(float x, unsigned short &hh, unsigned short &ll) {
    __nv_bfloat16 bh = __float2bfloat16(x);
    float hf = __bfloat162float(bh);
    __nv_bfloat16 bl = __float2bfloat16(x - hf);
    hh = __bfloat16_as_ushort(bh);
    ll = __bfloat16_as_ushort(bl);
}

__device__ __forceinline__ unsigned bfbits(float x) {
    return (unsigned)__bfloat16_as_ushort(__float2bfloat16(x));
}
__device__ __forceinline__ float bfval(float x) {
    return __bfloat162float(__float2bfloat16(x));
}
__device__ __forceinline__ unsigned packsplit(float x, float y, unsigned &lo) {
    float xh = bfval(x), yh = bfval(y);
    unsigned hi = bfbits(x) | (bfbits(y) << 16);
    lo = bfbits(x - xh) | (bfbits(y - yh) << 16);
    return hi;
}

// ---------------- grouped tf32 tensor-core GEMM (unchanged) ------------------
struct GroupArgs {
    const float* A[4];
    const float* B[4];
    void*        C[4];
    void*        Clo[4];
    int K[4];
    int N[4];
    int mode[4];
    int tstart[5];
};

__global__ __launch_bounds__(256, 2)
void mma_gemm_grouped(GroupArgs ga)
{
    __shared__ unsigned As[2][128][20];
    __shared__ unsigned Bs[2][16][136];

    int g = 0;
    while (blockIdx.y >= (unsigned)ga.tstart[g + 1]) g++;
    const float* __restrict__ A = ga.A[g];
    const float* __restrict__ B = ga.B[g];
    const int K = ga.K[g];
    const int N = ga.N[g];
    const int mode = ga.mode[g];

    const int tid  = threadIdx.x;
    const int lane = tid & 31;
    const int warp = tid >> 5;
    const int wm   = warp & 1;
    const int wn   = warp >> 1;
    const int m0   = blockIdx.x * 128;
    const int n0   = (blockIdx.y - ga.tstart[g]) * 128;
    const int fr   = lane >> 2;
    const int fc   = lane & 3;

    float acc[4][4][4];
#pragma unroll
    for (int mt = 0; mt < 4; mt++)
#pragma unroll
        for (int nt = 0; nt < 4; nt++)
#pragma unroll
            for (int i = 0; i < 4; i++) acc[mt][nt][i] = 0.f;

    float4 ra[2], rb[2];

    const int rowA0 = (tid + 0)   >> 2;   const int kcA0 = ((tid + 0)   & 3) * 4;
    const int rowA1 = (tid + 256) >> 2;   const int kcA1 = ((tid + 256) & 3) * 4;
    const int kkB0  = (tid + 0)   >> 5;   const int c4B0 = ((tid + 0)   & 31) * 4;
    const int kkB1  = (tid + 256) >> 5;   const int c4B1 = ((tid + 256) & 31) * 4;

#define LDG_TILE(k0)                                                            \
    {                                                                           \
        ra[0] = *(const float4*)&A[(size_t)(m0 + rowA0) * K + (k0) + kcA0];     \
        ra[1] = *(const float4*)&A[(size_t)(m0 + rowA1) * K + (k0) + kcA1];     \
        if (n0 + c4B0 < N)                                                      \
            rb[0] = *(const float4*)&B[(size_t)((k0) + kkB0) * N + n0 + c4B0];  \
        else rb[0] = make_float4(0.f, 0.f, 0.f, 0.f);                           \
        if (n0 + c4B1 < N)                                                      \
            rb[1] = *(const float4*)&B[(size_t)((k0) + kkB1) * N + n0 + c4B1];  \
        else rb[1] = make_float4(0.f, 0.f, 0.f, 0.f);                           \
    }

#define STS_TILE(buf)                                                           \
    {                                                                           \
        uint4 ua0 = make_uint4(f2tf(ra[0].x), f2tf(ra[0].y), f2tf(ra[0].z), f2tf(ra[0].w)); \
        uint4 ua1 = make_uint4(f2tf(ra[1].x), f2tf(ra[1].y), f2tf(ra[1].z), f2tf(ra[1].w)); \
        *(uint4*)&As[buf][rowA0][kcA0] = ua0;                                   \
        *(uint4*)&As[buf][rowA1][kcA1] = ua1;                                   \
        uint4 ub0 = make_uint4(f2tf(rb[0].x), f2tf(rb[0].y), f2tf(rb[0].z), f2tf(rb[0].w)); \
        uint4 ub1 = make_uint4(f2tf(rb[1].x), f2tf(rb[1].y), f2tf(rb[1].z), f2tf(rb[1].w)); \
        *(uint4*)&Bs[buf][kkB0][c4B0] = ub0;                                    \
        *(uint4*)&Bs[buf][kkB1][c4B1] = ub1;                                    \
    }

#define COMPUTE(buf)                                                            \
    {                                                                           \
        _Pragma("unroll")                                                       \
        for (int ks = 0; ks < 2; ks++) {                                        \
            unsigned af[4][4], bf[4][2];                                        \
            _Pragma("unroll")                                                   \
            for (int mt = 0; mt < 4; mt++) {                                    \
                int mr = wm * 64 + mt * 16 + fr;                                \
                af[mt][0] = As[buf][mr    ][ks * 8 + fc];                       \
                af[mt][1] = As[buf][mr + 8][ks * 8 + fc];                       \
                af[mt][2] = As[buf][mr    ][ks * 8 + fc + 4];                   \
                af[mt][3] = As[buf][mr + 8][ks * 8 + fc + 4];                   \
            }                                                                   \
            _Pragma("unroll")                                                   \
            for (int nt = 0; nt < 4; nt++) {                                    \
                int nc = wn * 32 + nt * 8 + fr;                                 \
                bf[nt][0] = Bs[buf][ks * 8 + fc    ][nc];                       \
                bf[nt][1] = Bs[buf][ks * 8 + fc + 4][nc];                       \
            }                                                                   \
            _Pragma("unroll")                                                   \
            for (int mt = 0; mt < 4; mt++)                                      \
                _Pragma("unroll")                                               \
                for (int nt = 0; nt < 4; nt++)                                  \
                    mma8(acc[mt][nt], af[mt], bf[nt]);                          \
        }                                                                       \
    }

    LDG_TILE(0);
    STS_TILE(0);
    __syncthreads();

    int buf = 0;
#pragma unroll 1
    for (int k0 = 16; k0 < K; k0 += 16) {
        LDG_TILE(k0);
        COMPUTE(buf);
        STS_TILE(buf ^ 1);
        __syncthreads();
        buf ^= 1;
    }
    COMPUTE(buf);

#pragma unroll
    for (int mt = 0; mt < 4; mt++) {
#pragma unroll
        for (int nt = 0; nt < 4; nt++) {
            int row = m0 + wm * 64 + mt * 16 + fr;
            int col = n0 + wn * 32 + nt * 8 + fc * 2;
            if (mode == 0) {
                float* Cf = (float*)ga.C[g];
                if (col < N) {
                    *(float2*)&Cf[(size_t)row * N + col] =
                        make_float2(acc[mt][nt][0], acc[mt][nt][1]);
                    *(float2*)&Cf[(size_t)(row + 8) * N + col] =
                        make_float2(acc[mt][nt][2], acc[mt][nt][3]);
                }
            } else if (mode == 1) {
                unsigned short* CH = (unsigned short*)ga.C[g];
                unsigned short* CL = (unsigned short*)ga.Clo[g];
                int hh = col >> 7, d = col & 127;
                int dp = (d & ~15) | pi16e(d & 15);
                size_t b0 = ((size_t)(hh * S_LEN + row)) * DQK + dp;
                size_t b1 = ((size_t)(hh * S_LEN + row + 8)) * DQK + dp;
                unsigned lo, hi;
                hi = packsplit(acc[mt][nt][0], acc[mt][nt][1], lo);
                *(unsigned*)&CH[b0] = hi; *(unsigned*)&CL[b0] = lo;
                hi = packsplit(acc[mt][nt][2], acc[mt][nt][3], lo);
                *(unsigned*)&CH[b1] = hi; *(unsigned*)&CL[b1] = lo;
            } else {
                float* Cf = (float*)ga.C[g];
                int hh = col >> 7, d = col & 127;
                *(float2*)&Cf[(size_t)((hh * S_LEN) + row)     * HD + d] =
                    make_float2(acc[mt][nt][0], acc[mt][nt][1]);
                *(float2*)&Cf[(size_t)((hh * S_LEN) + row + 8) * HD + d] =
                    make_float2(acc[mt][nt][2], acc[mt][nt][3]);
            }
        }
    }
#undef LDG_TILE
#undef STS_TILE
#undef COMPUTE
}

// ---------------- prep kernels (unchanged) -----------------------------------
__global__ void rope_q_kernel()
{
    int idx = blockIdx.x * blockDim.x + threadIdx.x;
    if (idx >= S_LEN * NH * 32) return;
    int i = idx & 31;
    int h = (idx >> 5) & 15;
    int t = idx >> 9;
    float invf = powf(10000.0f, -(2.0f * i) / 64.0f);
    float ang = (float)t * invf;
    float s, c;
    sincosf(ang, &s, &c);
    const float* x = g_qR + (size_t)t * (NH * DR) + h * DR;
    float x1 = x[i], x2 = x[i + 32];
    float r1 = x1 * c - x2 * s;
    float r2 = x2 * c + x1 * s;
    size_t base = ((size_t)(h * S_LEN + t)) * DQK;
    int d1 = 128 + i, d2 = 160 + i;
    int d1p = (d1 & ~15) | pi16(d1 & 15);
    int d2p = (d2 & ~15) | pi16(d2 & 15);
    unsigned short hh, ll;
    split2(r1, hh, ll); g_QH[base + d1p] = hh; g_QL[base + d1p] = ll;
    split2(r2, hh, ll); g_QH[base + d2p] = hh; g_QL[base + d2p] = ll;
}

__global__ void rope_k_kernel()
{
    int idx = blockIdx.x * blockDim.x + threadIdx.x;
    if (idx >= S_LEN * 32) return;
    int i = idx & 31;
    int t = idx >> 5;
    float invf = powf(10000.0f, -(2.0f * i) / 64.0f);
    float ang = (float)t * invf;
    float s, c;
    sincosf(ang, &s, &c);
    const float* x = g_kR + (size_t)t * DR;
    float r1 = x[i] * c - x[i + 32] * s;
    float r2 = x[i + 32] * c + x[i] * s;
    unsigned short h1, l1, h2, l2;
    split2(r1, h1, l1);
    split2(r2, h2, l2);
    int d1 = 128 + i, d2 = 160 + i;
    int d1p = (d1 & ~15) | pi16(d1 & 15);
    int d2p = (d2 & ~15) | pi16(d2 & 15);
#pragma unroll
    for (int h = 0; h < NH; h++) {
        size_t base = ((size_t)(h * S_LEN + t)) * DQK;
        g_KH[base + d1p] = h1; g_KL[base + d1p] = l1;
        g_KH[base + d2p] = h2; g_KL[base + d2p] = l2;
    }
}

__global__ __launch_bounds__(256)
void vtrans_kernel()
{
    __shared__ float sv[64][133];
    const int h  = blockIdx.y;
    const int s0 = blockIdx.x * 64;
    const int tid = threadIdx.x;
    const float* src = g_Vb + ((size_t)h * S_LEN + s0) * HD;
#pragma unroll
    for (int i = 0; i < 8; i++) {
        int idx = tid + i * 256;
        int r = idx >> 5, c4 = (idx & 31) * 4;
        float4 v = *(const float4*)&src[r * HD + c4];
        sv[r][c4] = v.x; sv[r][c4 + 1] = v.y; sv[r][c4 + 2] = v.z; sv[r][c4 + 3] = v.w;
    }
    __syncthreads();
    int sl = tid & 63, d0 = tid >> 6;
    int sp = s0 + ((sl & ~15) | pi16(sl & 15));
#pragma unroll
    for (int dd = 0; dd < 32; dd++) {
        int d = d0 * 32 + dd;
        unsigned short hh, ll;
        split2(sv[sl][d], hh, ll);
        size_t o = ((size_t)(h * HD + d)) * S_LEN + sp;
        g_VTH[o] = hh;
        g_VTL[o] = ll;
    }
}

// ---------------- bf16x3 flash attention: 8 warps x 16 rows ------------------
// No wn split: each warp computes 16 rows vs full BN=64 and full d=128.
// Softmax is warp-local (quad shuffles only). No O/red exchange.
// smem: QH[128][208]@0, QL@53248, KH[64][208]@106496, KL@133120,
//       VTH[128][80]@159744, VTL@180224
#define ATTN_SMEM 200704

__global__ __launch_bounds__(256, 1)
void attn_mma_kernel()
{
    extern __shared__ char smraw[];
    unsigned short* QH  = (unsigned short*)(smraw);
    unsigned short* QL  = (unsigned short*)(smraw + 53248);
    unsigned short* KH  = (unsigned short*)(smraw + 106496);
    unsigned short* KL  = (unsigned short*)(smraw + 133120);
    unsigned short* VTH = (unsigned short*)(smraw + 159744);
    unsigned short* VTL = (unsigned short*)(smraw + 180224);

    const int bid  = blockIdx.x;
    const int mb   = 15 - (bid >> 4);
    const int h    = bid & 15;
    const int m0   = mb * 128;
    const int tid  = threadIdx.x;
    const int lane = tid & 31;
    const int warp = tid >> 5;            // owns rows warp*16 .. +15
    const int g = lane >> 2, t = lane & 3;

    // stage Q (128 rows x 24 uint4, smem row stride 26)
    {
        const uint4* sH = (const uint4*)(g_QH + ((size_t)h * S_LEN + m0) * DQK);
        const uint4* sL = (const uint4*)(g_QL + ((size_t)h * S_LEN + m0) * DQK);
        uint4* dH = (uint4*)QH;
        uint4* dL = (uint4*)QL;
#pragma unroll
        for (int i = 0; i < 12; i++) {
            int idx = tid + i * 256;
            int r = idx / 24, u = idx - r * 24;
            dH[r * 26 + u] = sH[idx];
            dL[r * 26 + u] = sL[idx];
        }
    }

    float oacc[16][4];
#pragma unroll
    for (int nt = 0; nt < 16; nt++)
#pragma unroll
        for (int c = 0; c < 4; c++) oacc[nt][c] = 0.f;

    float mrow[2] = {-1e30f, -1e30f};
    float lrow[2] = {0.f, 0.f};

    const float scale = 0.07216878364870322f;
    const int ntiles = 2 * mb + 2;

    const uint4* KHg = (const uint4*)(g_KH + (size_t)h * S_LEN * DQK);
    const uint4* KLg = (const uint4*)(g_KL + (size_t)h * S_LEN * DQK);
    const uint4* VHg = (const uint4*)(g_VTH + (size_t)h * HD * S_LEN);
    const uint4* VLg = (const uint4*)(g_VTL + (size_t)h * HD * S_LEN);
    uint4* KH4 = (uint4*)KH;
    uint4* KL4 = (uint4*)KL;
    uint4* VH4 = (uint4*)VTH;
    uint4* VL4 = (uint4*)VTL;

#pragma unroll 1
    for (int tile = 0; tile < ntiles; tile++) {
        const int n0 = tile * 64;
        __syncthreads();

        {
            const uint4* sH = KHg + (size_t)n0 * 24;
            const uint4* sL = KLg + (size_t)n0 * 24;
#pragma unroll
            for (int i = 0; i < 6; i++) {
                int idx = tid + i * 256;
                int r = idx / 24, u = idx - r * 24;
                KH4[r * 26 + u] = sH[idx];
                KL4[r * 26 + u] = sL[idx];
            }
        }
        {
            const uint4* sH = VHg + (n0 >> 3);
            const uint4* sL = VLg + (n0 >> 3);
#pragma unroll
            for (int i = 0; i < 4; i++) {
                int idx = tid + i * 256;
                int d = idx >> 3, u = idx & 7;
                VH4[d * 10 + u] = sH[d * 256 + u];
                VL4[d * 10 + u] = sL[d * 256 + u];
            }
        }
        __syncthreads();

        // ---- S = Q K^T : warp rows x full 64 cols ----
        float sacc[8][4];
#pragma unroll
        for (int nt = 0; nt < 8; nt++)
#pragma unroll
            for (int c = 0; c < 4; c++) sacc[nt][c] = 0.f;

#pragma unroll
        for (int kt = 0; kt < 12; kt++) {
            unsigned ah[4], al[4];
            {
                int rb = (warp * 16 + g) * 208 + kt * 16 + 4 * t;
                uint2 a0 = *(const uint2*)&QH[rb];
                uint2 a1 = *(const uint2*)&QH[rb + 8 * 208];
                ah[0] = a0.x; ah[1] = a1.x; ah[2] = a0.y; ah[3] = a1.y;
                uint2 b0 = *(const uint2*)&QL[rb];
                uint2 b1 = *(const uint2*)&QL[rb + 8 * 208];
                al[0] = b0.x; al[1] = b1.x; al[2] = b0.y; al[3] = b1.y;
            }
#pragma unroll
            for (int nt = 0; nt < 8; nt++) {
                int nb = (nt * 8 + g) * 208 + kt * 16 + 4 * t;
                uint2 kb = *(const uint2*)&KH[nb];
                uint2 kl = *(const uint2*)&KL[nb];
                unsigned bh[2] = {kb.x, kb.y};
                unsigned bl[2] = {kl.x, kl.y};
                mma16(sacc[nt], ah, bh);
                mma16(sacc[nt], ah, bl);
                mma16(sacc[nt], al, bh);
            }
        }

        // ---- scale + causal mask ----
#pragma unroll
        for (int nt = 0; nt < 8; nt++)
#pragma unroll
            for (int c = 0; c < 4; c++) {
                int col = n0 + nt * 8 + 2 * t + (c & 1);
                int row = m0 + warp * 16 + g + (c >> 1) * 8;
                float v = sacc[nt][c] * scale;
                if (col > row) v = -1e30f;
                sacc[nt][c] = v;
            }

        // ---- warp-local online softmax (quad shuffles only) ----
        float alpha_[2];
#pragma unroll
        for (int hf = 0; hf < 2; hf++) {
            float pm = -1e30f;
#pragma unroll
            for (int nt = 0; nt < 8; nt++)
                pm = fmaxf(pm, fmaxf(sacc[nt][hf * 2], sacc[nt][hf * 2 + 1]));
            pm = fmaxf(pm, __shfl_xor_sync(0xffffffffu, pm, 1));
            pm = fmaxf(pm, __shfl_xor_sync(0xffffffffu, pm, 2));
            float mnew = fmaxf(mrow[hf], pm);
            alpha_[hf] = __expf(mrow[hf] - mnew);
            mrow[hf] = mnew;
            float ps = 0.f;
#pragma unroll
            for (int nt = 0; nt < 8; nt++)
#pragma unroll
                for (int k2 = 0; k2 < 2; k2++) {
                    int c = hf * 2 + k2;
                    float p = __expf(sacc[nt][c] - mnew);
                    sacc[nt][c] = p;
                    ps += p;
                }
            lrow[hf] = lrow[hf] * alpha_[hf] + ps;   // per-thread partial (own cols)
        }
#pragma unroll
        for (int nt = 0; nt < 16; nt++)
#pragma unroll
            for (int c = 0; c < 4; c++)
                oacc[nt][c] *= alpha_[c >> 1];

        // ---- O += P V : register P, full k=64, all 16 d-tiles ----
#pragma unroll
        for (int kt = 0; kt < 4; kt++) {
            unsigned aph[4], apl[4];
            aph[0] = packsplit(sacc[2 * kt][0],     sacc[2 * kt][1],     apl[0]);
            aph[1] = packsplit(sacc[2 * kt][2],     sacc[2 * kt][3],     apl[1]);
            aph[2] = packsplit(sacc[2 * kt + 1][0], sacc[2 * kt + 1][1], apl[2]);
            aph[3] = packsplit(sacc[2 * kt + 1][2], sacc[2 * kt + 1][3], apl[3]);
#pragma unroll
            for (int nt = 0; nt < 16; nt++) {
                int vb = (nt * 8 + g) * 80 + kt * 16 + 4 * t;
                uint2 vh = *(const uint2*)&VTH[vb];
                uint2 vl = *(const uint2*)&VTL[vb];
                unsigned bh[2] = {vh.x, vh.y};
                unsigned bl[2] = {vl.x, vl.y};
                mma16(oacc[nt], aph, bh);
                mma16(oacc[nt], aph, bl);
                mma16(oacc[nt], apl, bh);
            }
        }
    }

    // ---- epilogue: quad-reduce l, direct stores ----
#pragma unroll
    for (int hf = 0; hf < 2; hf++) {
        float lq = lrow[hf];
        lq += __shfl_xor_sync(0xffffffffu, lq, 1);
        lq += __shfl_xor_sync(0xffffffffu, lq, 2);
        float inv = 1.f / lq;
        int row = m0 + warp * 16 + hf * 8 + g;
#pragma unroll
        for (int nt = 0; nt < 16; nt++) {
            int col = nt * 8 + 2 * t;
            float v0 = oacc[nt][hf * 2]     * inv;
            float v1 = oacc[nt][hf * 2 + 1] * inv;
            *(float2*)&g_AO[(size_t)row * (NH * HD) + h * HD + col] = make_float2(v0, v1);
        }
    }
}

// ---------------- launch ----------------------------------------------------
extern "C" void kernel_launch(void* const* d_in, const int* in_sizes, int n_in,
                              void* d_out, int out_size)
{
    const float* X     = (const float*)d_in[0];
    const float* W_DKV = (const float*)d_in[2];
    const float* W_UK  = (const float*)d_in[3];
    const float* W_UV  = (const float*)d_in[4];
    const float* W_DQ  = (const float*)d_in[5];
    const float* W_UQ  = (const float*)d_in[6];
    const float* W_QR  = (const float*)d_in[7];
    const float* W_KR  = (const float*)d_in[8];
    const float* W_O   = (const float*)d_in[9];
    float* out = (float*)d_out;

    float *cKV, *cQ, *qR, *kR, *Vb, *AO;
    unsigned short *QHp, *QLp, *KHp, *KLp;
    cudaGetSymbolAddress((void**)&cKV, g_cKV);
    cudaGetSymbolAddress((void**)&cQ,  g_cQ);
    cudaGetSymbolAddress((void**)&qR,  g_qR);
    cudaGetSymbolAddress((void**)&kR,  g_kR);
    cudaGetSymbolAddress((void**)&Vb,  g_Vb);
    cudaGetSymbolAddress((void**)&AO,  g_AO);
    cudaGetSymbolAddress((void**)&QHp, g_QH);
    cudaGetSymbolAddress((void**)&QLp, g_QL);
    cudaGetSymbolAddress((void**)&KHp, g_KH);
    cudaGetSymbolAddress((void**)&KLp, g_KL);

    dim3 blk(256);

    // P1: X @ {W_DQ, W_DKV, W_KR}
    {
        GroupArgs ga = {};
        ga.A[0] = X;  ga.B[0] = W_DQ;  ga.C[0] = cQ;  ga.K[0] = HID_D; ga.N[0] = CQ;   ga.mode[0] = 0;
        ga.A[1] = X;  ga.B[1] = W_DKV; ga.C[1] = cKV; ga.K[1] = HID_D; ga.N[1] = CKV;  ga.mode[1] = 0;
        ga.A[2] = X;  ga.B[2] = W_KR;  ga.C[2] = kR;  ga.K[2] = HID_D; ga.N[2] = DR;   ga.mode[2] = 0;
        ga.tstart[0] = 0; ga.tstart[1] = 12; ga.tstart[2] = 16; ga.tstart[3] = 17; ga.tstart[4] = 17;
        mma_gemm_grouped<<<dim3(16, 17), blk>>>(ga);
    }
    // P2: {UQ->bf16 Q, QR->qR, UK->bf16 K, UV->V f32}
    {
        GroupArgs ga = {};
        ga.A[0] = cQ;  ga.B[0] = W_UQ; ga.C[0] = QHp; ga.Clo[0] = QLp; ga.K[0] = CQ;  ga.N[0] = NH * HD; ga.mode[0] = 1;
        ga.A[1] = cQ;  ga.B[1] = W_QR; ga.C[1] = qR;                   ga.K[1] = CQ;  ga.N[1] = NH * DR; ga.mode[1] = 0;
        ga.A[2] = cKV; ga.B[2] = W_UK; ga.C[2] = KHp; ga.Clo[2] = KLp; ga.K[2] = CKV; ga.N[2] = NH * HD; ga.mode[2] = 1;
        ga.A[3] = cKV; ga.B[3] = W_UV; ga.C[3] = Vb;                   ga.K[3] = CKV; ga.N[3] = NH * HD; ga.mode[3] = 2;
        ga.tstart[0] = 0; ga.tstart[1] = 16; ga.tstart[2] = 24; ga.tstart[3] = 40; ga.tstart[4] = 56;
        mma_gemm_grouped<<<dim3(16, 56), blk>>>(ga);
    }

    rope_q_kernel<<<(S_LEN * NH * 32) / 256, 256>>>();
    rope_k_kernel<<<(S_LEN * 32) / 256, 256>>>();
    vtrans_kernel<<<dim3(S_LEN / 64, NH), 256>>>();

    cudaFuncSetAttribute(attn_mma_kernel, cudaFuncAttributeMaxDynamicSharedMemorySize, ATTN_SMEM);
    attn_mma_kernel<<<256, 256, ATTN_SMEM>>>();

    // out = AO @ W_O
    {
        GroupArgs ga = {};
        ga.A[0] = AO; ga.B[0] = W_O; ga.C[0] = out; ga.K[0] = NH * HD; ga.N[0] = HID_D; ga.mode[0] = 0;
        ga.tstart[0] = 0; ga.tstart[1] = 16; ga.tstart[2] = 16; ga.tstart[3] = 16; ga.tstart[4] = 16;
        mma_gemm_grouped<<<dim3(16, 16), blk>>>(ga);
    }
}

// round 10
// speedup vs baseline: 1.1638x; 1.1116x over previous
#include <cuda_runtime.h>
#include <cuda_bf16.h>
#include <math.h>

#define S_LEN 2048
#define HID_D 2048
#define NH 16
#define HD 128
#define DR 64
#define DQK 192
#define CKV 512
#define CQ 1536

// ---------------- scratch ----------------------------------------------------
__device__ unsigned g_Xt  [S_LEN * HID_D];     // tf32 bits
__device__ unsigned g_Wdkv[HID_D * CKV];
__device__ unsigned g_Wuk [CKV * NH * HD];
__device__ unsigned g_Wuv [CKV * NH * HD];
__device__ unsigned g_Wdq [HID_D * CQ];
__device__ unsigned g_Wuq [CQ * NH * HD];
__device__ unsigned g_Wqr [CQ * NH * DR];
__device__ unsigned g_Wkr [HID_D * DR];
__device__ unsigned g_Wo  [NH * HD * HID_D];
__device__ unsigned g_cKVt[S_LEN * CKV];       // tf32 bits (P1 out, P2 in)
__device__ unsigned g_cQt [S_LEN * CQ];
__device__ unsigned g_AO  [S_LEN * NH * HD];   // tf32 bits (attn out, WO in)
__device__ float g_qR [S_LEN * NH * DR];
__device__ float g_kR [S_LEN * DR];
__device__ float g_Vb [NH * S_LEN * HD];
__device__ unsigned short g_QH[NH * S_LEN * DQK];   // k-paired bf16 hi
__device__ unsigned short g_QL[NH * S_LEN * DQK];
__device__ unsigned short g_KH[NH * S_LEN * DQK];
__device__ unsigned short g_KL[NH * S_LEN * DQK];
__device__ unsigned short g_VTH[NH * HD * S_LEN];   // [h][d][s] s-paired
__device__ unsigned short g_VTL[NH * HD * S_LEN];

// pair-permutation within a 16-chunk
__device__ __forceinline__ int pi16(int c) {
    return (c & 1) + (((c & 7) >> 1) << 2) + ((c >> 3) << 1);
}
__device__ __forceinline__ int pi16e(int c) {
    return (((c & 7) >> 1) << 2) + ((c >> 3) << 1);
}

// ---------------- tf32 / bf16 helpers ---------------------------------------
__device__ __forceinline__ unsigned f2tf(float x) {
    unsigned u;
    asm("cvt.rna.tf32.f32 %0, %1;" : "=r"(u) : "f"(x));
    return u;
}

__device__ __forceinline__ void mma8(float c[4], const unsigned a[4], const unsigned b[2]) {
    asm volatile(
        "mma.sync.aligned.m16n8k8.row.col.f32.tf32.tf32.f32 "
        "{%0,%1,%2,%3}, {%4,%5,%6,%7}, {%8,%9}, {%0,%1,%2,%3};\n"
        : "+f"(c[0]), "+f"(c[1]), "+f"(c[2]), "+f"(c[3])
        : "r"(a[0]), "r"(a[1]), "r"(a[2]), "r"(a[3]), "r"(b[0]), "r"(b[1]));
}

__device__ __forceinline__ void mma16(float c[4], const unsigned a[4], const unsigned b[2]) {
    asm volatile(
        "mma.sync.aligned.m16n8k16.row.col.f32.bf16.bf16.f32 "
        "{%0,%1,%2,%3}, {%4,%5,%6,%7}, {%8,%9}, {%0,%1,%2,%3};\n"
        : "+f"(c[0]), "+f"(c[1]), "+f"(c[2]), "+f"(c[3])
        : "r"(a[0]), "r"(a[1]), "r"(a[2]), "r"(a[3]), "r"(b[0]), "r"(b[1]));
}

__device__ __forceinline__ void split2(float x, unsigned short &hh, unsigned short &ll) {
    __nv_bfloat16 bh = __float2bfloat16(x);
    float hf = __bfloat162float(bh);
    __nv_bfloat16 bl = __float2bfloat16(x - hf);
    hh = __bfloat16_as_ushort(bh);
    ll = __bfloat16_as_ushort(bl);
}

__device__ __forceinline__ unsigned bfbits(float x) {
    return (unsigned)__bfloat16_as_ushort(__float2bfloat16(x));
}
__device__ __forceinline__ float bfval(float x) {
    return __bfloat162float(__float2bfloat16(x));
}
__device__ __forceinline__ unsigned packsplit(float x, float y, unsigned &lo) {
    float xh = bfval(x), yh = bfval(y);
    unsigned hi = bfbits(x) | (bfbits(y) << 16);
    lo = bfbits(x - xh) | (bfbits(y - yh) << 16);
    return hi;
}

__device__ __forceinline__ void cp16(unsigned* dst_smem, const unsigned* src, bool pred) {
    unsigned saddr = (unsigned)__cvta_generic_to_shared(dst_smem);
    int sz = pred ? 16 : 0;
    asm volatile("cp.async.cg.shared.global [%0], [%1], 16, %2;\n"
                 :: "r"(saddr), "l"(src), "r"(sz));
}

// ---------------- preconvert: f32 -> tf32 bits -------------------------------
struct CvtArgs {
    const float* src[9];
    unsigned*    dst[9];
    int tstart[10];
};

__global__ __launch_bounds__(256)
void cvt_kernel(CvtArgs ca)
{
    int g = 0;
    while ((int)blockIdx.x >= ca.tstart[g + 1]) g++;
    int idx = (blockIdx.x - ca.tstart[g]) * 1024 + threadIdx.x * 4;
    float4 v = *(const float4*)&ca.src[g][idx];
    uint4 u = make_uint4(f2tf(v.x), f2tf(v.y), f2tf(v.z), f2tf(v.w));
    *(uint4*)&ca.dst[g][idx] = u;
}

// ---------------- grouped tf32 GEMM with cp.async pipeline -------------------
// A, B already tf32-bit u32. 128x128 tile, BK=16, 3-stage cp.async.
// modes: 0 = f32 row-major (col<N guard), 1 = bf16 hi/lo head-split 192,
//        2 = f32 head-split 128, 3 = tf32-bits row-major
#define GSTAGES 3
#define GEMM_SMEM (GSTAGES * (2560 + 2176) * 4)

struct GroupArgs {
    const unsigned* A[4];
    const unsigned* B[4];
    void*        C[4];
    void*        Clo[4];
    int K[4];
    int N[4];
    int mode[4];
    int tstart[5];
};

__global__ __launch_bounds__(256, 2)
void mma_gemm_grouped(GroupArgs ga)
{
    extern __shared__ unsigned gsm[];
    unsigned* As = gsm;                      // [st][128][20]
    unsigned* Bs = gsm + GSTAGES * 2560;     // [st][16][136]

    int g = 0;
    while (blockIdx.y >= (unsigned)ga.tstart[g + 1]) g++;
    const unsigned* __restrict__ A = ga.A[g];
    const unsigned* __restrict__ B = ga.B[g];
    const int K = ga.K[g];
    const int N = ga.N[g];
    const int mode = ga.mode[g];

    const int tid  = threadIdx.x;
    const int lane = tid & 31;
    const int warp = tid >> 5;
    const int wm   = warp & 1;
    const int wn   = warp >> 1;
    const int m0   = blockIdx.x * 128;
    const int n0   = (blockIdx.y - ga.tstart[g]) * 128;
    const int fr   = lane >> 2;
    const int fc   = lane & 3;

    float acc[4][4][4];
#pragma unroll
    for (int mt = 0; mt < 4; mt++)
#pragma unroll
        for (int nt = 0; nt < 4; nt++)
#pragma unroll
            for (int i = 0; i < 4; i++) acc[mt][nt][i] = 0.f;

    const int rowA0 = (tid + 0)   >> 2;   const int kcA0 = ((tid + 0)   & 3) * 4;
    const int rowA1 = (tid + 256) >> 2;   const int kcA1 = ((tid + 256) & 3) * 4;
    const int kkB0  = (tid + 0)   >> 5;   const int c4B0 = ((tid + 0)   & 31) * 4;
    const int kkB1  = (tid + 256) >> 5;   const int c4B1 = ((tid + 256) & 31) * 4;
    const bool pb0 = (n0 + c4B0 < N);
    const bool pb1 = (n0 + c4B1 < N);

    const int ktiles = K >> 4;

#define GLOAD(kt, st)                                                           \
    {                                                                           \
        cp16(&As[(st) * 2560 + rowA0 * 20 + kcA0],                              \
             &A[(size_t)(m0 + rowA0) * K + (kt) * 16 + kcA0], true);            \
        cp16(&As[(st) * 2560 + rowA1 * 20 + kcA1],                              \
             &A[(size_t)(m0 + rowA1) * K + (kt) * 16 + kcA1], true);            \
        cp16(&Bs[(st) * 2176 + kkB0 * 136 + c4B0],                              \
             &B[(size_t)((kt) * 16 + kkB0) * N + n0 + c4B0], pb0);              \
        cp16(&Bs[(st) * 2176 + kkB1 * 136 + c4B1],                              \
             &B[(size_t)((kt) * 16 + kkB1) * N + n0 + c4B1], pb1);              \
    }

#pragma unroll
    for (int s = 0; s < GSTAGES - 1; s++) {
        GLOAD(s, s);
        asm volatile("cp.async.commit_group;\n");
    }

#pragma unroll 1
    for (int i = 0; i < ktiles; i++) {
        asm volatile("cp.async.wait_group %0;\n" :: "n"(GSTAGES - 2));
        __syncthreads();
        int nf = i + GSTAGES - 1;
        if (nf < ktiles) GLOAD(nf, nf % GSTAGES);
        asm volatile("cp.async.commit_group;\n");

        const unsigned* Asb = As + (i % GSTAGES) * 2560;
        const unsigned* Bsb = Bs + (i % GSTAGES) * 2176;
#pragma unroll
        for (int ks = 0; ks < 2; ks++) {
            unsigned af[4][4], bf[4][2];
#pragma unroll
            for (int mt = 0; mt < 4; mt++) {
                int mr = wm * 64 + mt * 16 + fr;
                af[mt][0] = Asb[mr * 20 + ks * 8 + fc];
                af[mt][1] = Asb[(mr + 8) * 20 + ks * 8 + fc];
                af[mt][2] = Asb[mr * 20 + ks * 8 + fc + 4];
                af[mt][3] = Asb[(mr + 8) * 20 + ks * 8 + fc + 4];
            }
#pragma unroll
            for (int nt = 0; nt < 4; nt++) {
                int nc = wn * 32 + nt * 8 + fr;
                bf[nt][0] = Bsb[(ks * 8 + fc) * 136 + nc];
                bf[nt][1] = Bsb[(ks * 8 + fc + 4) * 136 + nc];
            }
#pragma unroll
            for (int mt = 0; mt < 4; mt++)
#pragma unroll
                for (int nt = 0; nt < 4; nt++)
                    mma8(acc[mt][nt], af[mt], bf[nt]);
        }
    }
#undef GLOAD

    // ---- epilogue ----
#pragma unroll
    for (int mt = 0; mt < 4; mt++) {
#pragma unroll
        for (int nt = 0; nt < 4; nt++) {
            int row = m0 + wm * 64 + mt * 16 + fr;
            int col = n0 + wn * 32 + nt * 8 + fc * 2;
            if (mode == 0) {
                float* Cf = (float*)ga.C[g];
                if (col < N) {
                    *(float2*)&Cf[(size_t)row * N + col] =
                        make_float2(acc[mt][nt][0], acc[mt][nt][1]);
                    *(float2*)&Cf[(size_t)(row + 8) * N + col] =
                        make_float2(acc[mt][nt][2], acc[mt][nt][3]);
                }
            } else if (mode == 1) {
                unsigned short* CH = (unsigned short*)ga.C[g];
                unsigned short* CL = (unsigned short*)ga.Clo[g];
                int hh = col >> 7, d = col & 127;
                int dp = (d & ~15) | pi16e(d & 15);
                size_t b0 = ((size_t)(hh * S_LEN + row)) * DQK + dp;
                size_t b1 = ((size_t)(hh * S_LEN + row + 8)) * DQK + dp;
                unsigned lo, hi;
                hi = packsplit(acc[mt][nt][0], acc[mt][nt][1], lo);
                *(unsigned*)&CH[b0] = hi; *(unsigned*)&CL[b0] = lo;
                hi = packsplit(acc[mt][nt][2], acc[mt][nt][3], lo);
                *(unsigned*)&CH[b1] = hi; *(unsigned*)&CL[b1] = lo;
            } else if (mode == 2) {
                float* Cf = (float*)ga.C[g];
                int hh = col >> 7, d = col & 127;
                *(float2*)&Cf[(size_t)((hh * S_LEN) + row)     * HD + d] =
                    make_float2(acc[mt][nt][0], acc[mt][nt][1]);
                *(float2*)&Cf[(size_t)((hh * S_LEN) + row + 8) * HD + d] =
                    make_float2(acc[mt][nt][2], acc[mt][nt][3]);
            } else {
                unsigned* Cu = (unsigned*)ga.C[g];
                *(uint2*)&Cu[(size_t)row * N + col] =
                    make_uint2(f2tf(acc[mt][nt][0]), f2tf(acc[mt][nt][1]));
                *(uint2*)&Cu[(size_t)(row + 8) * N + col] =
                    make_uint2(f2tf(acc[mt][nt][2]), f2tf(acc[mt][nt][3]));
            }
        }
    }
}

// ---------------- prep kernels -----------------------------------------------
__global__ void rope_q_kernel()
{
    int idx = blockIdx.x * blockDim.x + threadIdx.x;
    if (idx >= S_LEN * NH * 32) return;
    int i = idx & 31;
    int h = (idx >> 5) & 15;
    int t = idx >> 9;
    float invf = powf(10000.0f, -(2.0f * i) / 64.0f);
    float ang = (float)t * invf;
    float s, c;
    sincosf(ang, &s, &c);
    const float* x = g_qR + (size_t)t * (NH * DR) + h * DR;
    float x1 = x[i], x2 = x[i + 32];
    float r1 = x1 * c - x2 * s;
    float r2 = x2 * c + x1 * s;
    size_t base = ((size_t)(h * S_LEN + t)) * DQK;
    int d1 = 128 + i, d2 = 160 + i;
    int d1p = (d1 & ~15) | pi16(d1 & 15);
    int d2p = (d2 & ~15) | pi16(d2 & 15);
    unsigned short hh, ll;
    split2(r1, hh, ll); g_QH[base + d1p] = hh; g_QL[base + d1p] = ll;
    split2(r2, hh, ll); g_QH[base + d2p] = hh; g_QL[base + d2p] = ll;
}

__global__ void rope_k_kernel()
{
    int idx = blockIdx.x * blockDim.x + threadIdx.x;
    if (idx >= S_LEN * 32) return;
    int i = idx & 31;
    int t = idx >> 5;
    float invf = powf(10000.0f, -(2.0f * i) / 64.0f);
    float ang = (float)t * invf;
    float s, c;
    sincosf(ang, &s, &c);
    const float* x = g_kR + (size_t)t * DR;
    float r1 = x[i] * c - x[i + 32] * s;
    float r2 = x[i + 32] * c + x[i] * s;
    unsigned short h1, l1, h2, l2;
    split2(r1, h1, l1);
    split2(r2, h2, l2);
    int d1 = 128 + i, d2 = 160 + i;
    int d1p = (d1 & ~15) | pi16(d1 & 15);
    int d2p = (d2 & ~15) | pi16(d2 & 15);
#pragma unroll
    for (int h = 0; h < NH; h++) {
        size_t base = ((size_t)(h * S_LEN + t)) * DQK;
        g_KH[base + d1p] = h1; g_KL[base + d1p] = l1;
        g_KH[base + d2p] = h2; g_KL[base + d2p] = l2;
    }
}

__global__ __launch_bounds__(256)
void vtrans_kernel()
{
    __shared__ float sv[64][133];
    const int h  = blockIdx.y;
    const int s0 = blockIdx.x * 64;
    const int tid = threadIdx.x;
    const float* src = g_Vb + ((size_t)h * S_LEN + s0) * HD;
#pragma unroll
    for (int i = 0; i < 8; i++) {
        int idx = tid + i * 256;
        int r = idx >> 5, c4 = (idx & 31) * 4;
        float4 v = *(const float4*)&src[r * HD + c4];
        sv[r][c4] = v.x; sv[r][c4 + 1] = v.y; sv[r][c4 + 2] = v.z; sv[r][c4 + 3] = v.w;
    }
    __syncthreads();
    int sl = tid & 63, d0 = tid >> 6;
    int sp = s0 + ((sl & ~15) | pi16(sl & 15));
#pragma unroll
    for (int dd = 0; dd < 32; dd++) {
        int d = d0 * 32 + dd;
        unsigned short hh, ll;
        split2(sv[sl][d], hh, ll);
        size_t o = ((size_t)(h * HD + d)) * S_LEN + sp;
        g_VTH[o] = hh;
        g_VTL[o] = ll;
    }
}

// ---------------- bf16x3 flash attention: 8 warps x 16 rows ------------------
#define ATTN_SMEM 200704

__global__ __launch_bounds__(256, 1)
void attn_mma_kernel()
{
    extern __shared__ char smraw[];
    unsigned short* QH  = (unsigned short*)(smraw);
    unsigned short* QL  = (unsigned short*)(smraw + 53248);
    unsigned short* KH  = (unsigned short*)(smraw + 106496);
    unsigned short* KL  = (unsigned short*)(smraw + 133120);
    unsigned short* VTH = (unsigned short*)(smraw + 159744);
    unsigned short* VTL = (unsigned short*)(smraw + 180224);

    const int bid  = blockIdx.x;
    const int mb   = 15 - (bid >> 4);
    const int h    = bid & 15;
    const int m0   = mb * 128;
    const int tid  = threadIdx.x;
    const int lane = tid & 31;
    const int warp = tid >> 5;
    const int g = lane >> 2, t = lane & 3;

    {
        const uint4* sH = (const uint4*)(g_QH + ((size_t)h * S_LEN + m0) * DQK);
        const uint4* sL = (const uint4*)(g_QL + ((size_t)h * S_LEN + m0) * DQK);
        uint4* dH = (uint4*)QH;
        uint4* dL = (uint4*)QL;
#pragma unroll
        for (int i = 0; i < 12; i++) {
            int idx = tid + i * 256;
            int r = idx / 24, u = idx - r * 24;
            dH[r * 26 + u] = sH[idx];
            dL[r * 26 + u] = sL[idx];
        }
    }

    float oacc[16][4];
#pragma unroll
    for (int nt = 0; nt < 16; nt++)
#pragma unroll
        for (int c = 0; c < 4; c++) oacc[nt][c] = 0.f;

    float mrow[2] = {-1e30f, -1e30f};
    float lrow[2] = {0.f, 0.f};

    const float scale = 0.07216878364870322f;
    const int ntiles = 2 * mb + 2;

    const uint4* KHg = (const uint4*)(g_KH + (size_t)h * S_LEN * DQK);
    const uint4* KLg = (const uint4*)(g_KL + (size_t)h * S_LEN * DQK);
    const uint4* VHg = (const uint4*)(g_VTH + (size_t)h * HD * S_LEN);
    const uint4* VLg = (const uint4*)(g_VTL + (size_t)h * HD * S_LEN);
    uint4* KH4 = (uint4*)KH;
    uint4* KL4 = (uint4*)KL;
    uint4* VH4 = (uint4*)VTH;
    uint4* VL4 = (uint4*)VTL;

#pragma unroll 1
    for (int tile = 0; tile < ntiles; tile++) {
        const int n0 = tile * 64;
        __syncthreads();

        {
            const uint4* sH = KHg + (size_t)n0 * 24;
            const uint4* sL = KLg + (size_t)n0 * 24;
#pragma unroll
            for (int i = 0; i < 6; i++) {
                int idx = tid + i * 256;
                int r = idx / 24, u = idx - r * 24;
                KH4[r * 26 + u] = sH[idx];
                KL4[r * 26 + u] = sL[idx];
            }
        }
        {
            const uint4* sH = VHg + (n0 >> 3);
            const uint4* sL = VLg + (n0 >> 3);
#pragma unroll
            for (int i = 0; i < 4; i++) {
                int idx = tid + i * 256;
                int d = idx >> 3, u = idx & 7;
                VH4[d * 10 + u] = sH[d * 256 + u];
                VL4[d * 10 + u] = sL[d * 256 + u];
            }
        }
        __syncthreads();

        float sacc[8][4];
#pragma unroll
        for (int nt = 0; nt < 8; nt++)
#pragma unroll
            for (int c = 0; c < 4; c++) sacc[nt][c] = 0.f;

#pragma unroll
        for (int kt = 0; kt < 12; kt++) {
            unsigned ah[4], al[4];
            {
                int rb = (warp * 16 + g) * 208 + kt * 16 + 4 * t;
                uint2 a0 = *(const uint2*)&QH[rb];
                uint2 a1 = *(const uint2*)&QH[rb + 8 * 208];
                ah[0] = a0.x; ah[1] = a1.x; ah[2] = a0.y; ah[3] = a1.y;
                uint2 b0 = *(const uint2*)&QL[rb];
                uint2 b1 = *(const uint2*)&QL[rb + 8 * 208];
                al[0] = b0.x; al[1] = b1.x; al[2] = b0.y; al[3] = b1.y;
            }
#pragma unroll
            for (int nt = 0; nt < 8; nt++) {
                int nb = (nt * 8 + g) * 208 + kt * 16 + 4 * t;
                uint2 kb = *(const uint2*)&KH[nb];
                uint2 kl = *(const uint2*)&KL[nb];
                unsigned bh[2] = {kb.x, kb.y};
                unsigned bl[2] = {kl.x, kl.y};
                mma16(sacc[nt], ah, bh);
                mma16(sacc[nt], ah, bl);
                mma16(sacc[nt], al, bh);
            }
        }

#pragma unroll
        for (int nt = 0; nt < 8; nt++)
#pragma unroll
            for (int c = 0; c < 4; c++) {
                int col = n0 + nt * 8 + 2 * t + (c & 1);
                int row = m0 + warp * 16 + g + (c >> 1) * 8;
                float v = sacc[nt][c] * scale;
                if (col > row) v = -1e30f;
                sacc[nt][c] = v;
            }

        float alpha_[2];
#pragma unroll
        for (int hf = 0; hf < 2; hf++) {
            float pm = -1e30f;
#pragma unroll
            for (int nt = 0; nt < 8; nt++)
                pm = fmaxf(pm, fmaxf(sacc[nt][hf * 2], sacc[nt][hf * 2 + 1]));
            pm = fmaxf(pm, __shfl_xor_sync(0xffffffffu, pm, 1));
            pm = fmaxf(pm, __shfl_xor_sync(0xffffffffu, pm, 2));
            float mnew = fmaxf(mrow[hf], pm);
            alpha_[hf] = __expf(mrow[hf] - mnew);
            mrow[hf] = mnew;
            float ps = 0.f;
#pragma unroll
            for (int nt = 0; nt < 8; nt++)
#pragma unroll
                for (int k2 = 0; k2 < 2; k2++) {
                    int c = hf * 2 + k2;
                    float p = __expf(sacc[nt][c] - mnew);
                    sacc[nt][c] = p;
                    ps += p;
                }
            lrow[hf] = lrow[hf] * alpha_[hf] + ps;
        }
#pragma unroll
        for (int nt = 0; nt < 16; nt++)
#pragma unroll
            for (int c = 0; c < 4; c++)
                oacc[nt][c] *= alpha_[c >> 1];

#pragma unroll
        for (int kt = 0; kt < 4; kt++) {
            unsigned aph[4], apl[4];
            aph[0] = packsplit(sacc[2 * kt][0],     sacc[2 * kt][1],     apl[0]);
            aph[1] = packsplit(sacc[2 * kt][2],     sacc[2 * kt][3],     apl[1]);
            aph[2] = packsplit(sacc[2 * kt + 1][0], sacc[2 * kt + 1][1], apl[2]);
            aph[3] = packsplit(sacc[2 * kt + 1][2], sacc[2 * kt + 1][3], apl[3]);
#pragma unroll
            for (int nt = 0; nt < 16; nt++) {
                int vb = (nt * 8 + g) * 80 + kt * 16 + 4 * t;
                uint2 vh = *(const uint2*)&VTH[vb];
                uint2 vl = *(const uint2*)&VTL[vb];
                unsigned bh[2] = {vh.x, vh.y};
                unsigned bl[2] = {vl.x, vl.y};
                mma16(oacc[nt], aph, bh);
                mma16(oacc[nt], aph, bl);
                mma16(oacc[nt], apl, bh);
            }
        }
    }

    // ---- epilogue: quad-reduce l, store AO as tf32 bits ----
#pragma unroll
    for (int hf = 0; hf < 2; hf++) {
        float lq = lrow[hf];
        lq += __shfl_xor_sync(0xffffffffu, lq, 1);
        lq += __shfl_xor_sync(0xffffffffu, lq, 2);
        float inv = 1.f / lq;
        int row = m0 + warp * 16 + hf * 8 + g;
#pragma unroll
        for (int nt = 0; nt < 16; nt++) {
            int col = nt * 8 + 2 * t;
            float v0 = oacc[nt][hf * 2]     * inv;
            float v1 = oacc[nt][hf * 2 + 1] * inv;
            *(uint2*)&g_AO[(size_t)row * (NH * HD) + h * HD + col] =
                make_uint2(f2tf(v0), f2tf(v1));
        }
    }
}

// ---------------- launch ----------------------------------------------------
extern "C" void kernel_launch(void* const* d_in, const int* in_sizes, int n_in,
                              void* d_out, int out_size)
{
    const float* X     = (const float*)d_in[0];
    const float* W_DKV = (const float*)d_in[2];
    const float* W_UK  = (const float*)d_in[3];
    const float* W_UV  = (const float*)d_in[4];
    const float* W_DQ  = (const float*)d_in[5];
    const float* W_UQ  = (const float*)d_in[6];
    const float* W_QR  = (const float*)d_in[7];
    const float* W_KR  = (const float*)d_in[8];
    const float* W_O   = (const float*)d_in[9];
    float* out = (float*)d_out;

    unsigned *Xt, *Wdkv, *Wuk, *Wuv, *Wdq, *Wuq, *Wqr, *Wkr, *Wo;
    unsigned *cKVt, *cQt, *AO;
    float *qR, *kR, *Vb;
    unsigned short *QHp, *QLp, *KHp, *KLp;
    cudaGetSymbolAddress((void**)&Xt,   g_Xt);
    cudaGetSymbolAddress((void**)&Wdkv, g_Wdkv);
    cudaGetSymbolAddress((void**)&Wuk,  g_Wuk);
    cudaGetSymbolAddress((void**)&Wuv,  g_Wuv);
    cudaGetSymbolAddress((void**)&Wdq,  g_Wdq);
    cudaGetSymbolAddress((void**)&Wuq,  g_Wuq);
    cudaGetSymbolAddress((void**)&Wqr,  g_Wqr);
    cudaGetSymbolAddress((void**)&Wkr,  g_Wkr);
    cudaGetSymbolAddress((void**)&Wo,   g_Wo);
    cudaGetSymbolAddress((void**)&cKVt, g_cKVt);
    cudaGetSymbolAddress((void**)&cQt,  g_cQt);
    cudaGetSymbolAddress((void**)&AO,   g_AO);
    cudaGetSymbolAddress((void**)&qR,   g_qR);
    cudaGetSymbolAddress((void**)&kR,   g_kR);
    cudaGetSymbolAddress((void**)&Vb,   g_Vb);
    cudaGetSymbolAddress((void**)&QHp,  g_QH);
    cudaGetSymbolAddress((void**)&QLp,  g_QL);
    cudaGetSymbolAddress((void**)&KHp,  g_KH);
    cudaGetSymbolAddress((void**)&KLp,  g_KL);

    dim3 blk(256);

    // 0) preconvert all GEMM operands to tf32 bits
    {
        CvtArgs ca = {};
        const float* srcs[9] = {X, W_DKV, W_UK, W_UV, W_DQ, W_UQ, W_QR, W_KR, W_O};
        unsigned* dsts[9] = {Xt, Wdkv, Wuk, Wuv, Wdq, Wuq, Wqr, Wkr, Wo};
        int sizes[9] = {S_LEN * HID_D, HID_D * CKV, CKV * NH * HD, CKV * NH * HD,
                        HID_D * CQ, CQ * NH * HD, CQ * NH * DR, HID_D * DR,
                        NH * HD * HID_D};
        int acc = 0;
        for (int i = 0; i < 9; i++) {
            ca.src[i] = srcs[i];
            ca.dst[i] = dsts[i];
            ca.tstart[i] = acc;
            acc += sizes[i] / 1024;
        }
        ca.tstart[9] = acc;
        cvt_kernel<<<acc, blk>>>(ca);
    }

    cudaFuncSetAttribute(mma_gemm_grouped,
                         cudaFuncAttributeMaxDynamicSharedMemorySize, GEMM_SMEM);

    // P1: Xt @ {Wdq->cQt(tf32), Wdkv->cKVt(tf32), Wkr->kR(f32)}
    {
        GroupArgs ga = {};
        ga.A[0] = Xt; ga.B[0] = Wdq;  ga.C[0] = cQt;  ga.K[0] = HID_D; ga.N[0] = CQ;  ga.mode[0] = 3;
        ga.A[1] = Xt; ga.B[1] = Wdkv; ga.C[1] = cKVt; ga.K[1] = HID_D; ga.N[1] = CKV; ga.mode[1] = 3;
        ga.A[2] = Xt; ga.B[2] = Wkr;  ga.C[2] = kR;   ga.K[2] = HID_D; ga.N[2] = DR;  ga.mode[2] = 0;
        ga.tstart[0] = 0; ga.tstart[1] = 12; ga.tstart[2] = 16; ga.tstart[3] = 17; ga.tstart[4] = 17;
        mma_gemm_grouped<<<dim3(16, 17), blk, GEMM_SMEM>>>(ga);
    }
    // P2: {Wuq->bf16 Q, Wqr->qR(f32), Wuk->bf16 K, Wuv->V(f32)}
    {
        GroupArgs ga = {};
        ga.A[0] = cQt;  ga.B[0] = Wuq; ga.C[0] = QHp; ga.Clo[0] = QLp; ga.K[0] = CQ;  ga.N[0] = NH * HD; ga.mode[0] = 1;
        ga.A[1] = cQt;  ga.B[1] = Wqr; ga.C[1] = qR;                   ga.K[1] = CQ;  ga.N[1] = NH * DR; ga.mode[1] = 0;
        ga.A[2] = cKVt; ga.B[2] = Wuk; ga.C[2] = KHp; ga.Clo[2] = KLp; ga.K[2] = CKV; ga.N[2] = NH * HD; ga.mode[2] = 1;
        ga.A[3] = cKVt; ga.B[3] = Wuv; ga.C[3] = Vb;                   ga.K[3] = CKV; ga.N[3] = NH * HD; ga.mode[3] = 2;
        ga.tstart[0] = 0; ga.tstart[1] = 16; ga.tstart[2] = 24; ga.tstart[3] = 40; ga.tstart[4] = 56;
        mma_gemm_grouped<<<dim3(16, 56), blk, GEMM_SMEM>>>(ga);
    }

    rope_q_kernel<<<(S_LEN * NH * 32) / 256, 256>>>();
    rope_k_kernel<<<(S_LEN * 32) / 256, 256>>>();
    vtrans_kernel<<<dim3(S_LEN / 64, NH), 256>>>();

    cudaFuncSetAttribute(attn_mma_kernel, cudaFuncAttributeMaxDynamicSharedMemorySize, ATTN_SMEM);
    attn_mma_kernel<<<256, 256, ATTN_SMEM>>>();

    // WO: AO(tf32) @ Wo -> out (f32)
    {
        GroupArgs ga = {};
        ga.A[0] = AO; ga.B[0] = Wo; ga.C[0] = out; ga.K[0] = NH * HD; ga.N[0] = HID_D; ga.mode[0] = 0;
        ga.tstart[0] = 0; ga.tstart[1] = 16; ga.tstart[2] = 16; ga.tstart[3] = 16; ga.tstart[4] = 16;
        mma_gemm_grouped<<<dim3(16, 16), blk, GEMM_SMEM>>>(ga);
    }
}

// round 11
// speedup vs baseline: 1.1989x; 1.0301x over previous
#include <cuda_runtime.h>
#include <cuda_bf16.h>
#include <math.h>

#define S_LEN 2048
#define HID_D 2048
#define NH 16
#define HD 128
#define DR 64
#define DQK 192
#define CKV 512
#define CQ 1536

// ---------------- scratch ----------------------------------------------------
__device__ unsigned g_Xt  [S_LEN * HID_D];     // tf32 bits, k-pair-permuted (A operand)
__device__ unsigned g_Wdkv[HID_D * CKV];
__device__ unsigned g_Wuk [CKV * NH * HD];
__device__ unsigned g_Wuv [CKV * NH * HD];
__device__ unsigned g_Wdq [HID_D * CQ];
__device__ unsigned g_Wuq [CQ * NH * HD];
__device__ unsigned g_Wqr [CQ * NH * DR];
__device__ unsigned g_Wkr [HID_D * DR];
__device__ unsigned g_Wo  [NH * HD * HID_D];
__device__ unsigned g_cKVt[S_LEN * CKV];       // tf32 bits, permuted (A)
__device__ unsigned g_cQt [S_LEN * CQ];        // tf32 bits, permuted (A)
__device__ unsigned g_AO  [S_LEN * NH * HD];   // tf32 bits, permuted (A of WO)
__device__ float g_qR [S_LEN * NH * DR];
__device__ float g_kR [S_LEN * DR];
__device__ float g_Vb [NH * S_LEN * HD];
__device__ unsigned short g_QH[NH * S_LEN * DQK];   // k-paired bf16 hi
__device__ unsigned short g_QL[NH * S_LEN * DQK];
__device__ unsigned short g_KH[NH * S_LEN * DQK];
__device__ unsigned short g_KL[NH * S_LEN * DQK];
__device__ unsigned short g_VTH[NH * HD * S_LEN];   // [h][d][s] s-paired
__device__ unsigned short g_VTL[NH * HD * S_LEN];

// bf16 pair-permutation within a 16-chunk
__device__ __forceinline__ int pi16(int c) {
    return (c & 1) + (((c & 7) >> 1) << 2) + ((c >> 3) << 1);
}
__device__ __forceinline__ int pi16e(int c) {
    return (((c & 7) >> 1) << 2) + ((c >> 3) << 1);
}
// tf32 A-operand pair-permutation within an 8-chunk: k c -> offset (c&3)*2 + (c>>2)
__device__ __forceinline__ int pa8(int c) {
    return ((c & 3) << 1) | (c >> 2);
}

// ---------------- tf32 / bf16 helpers ---------------------------------------
__device__ __forceinline__ unsigned f2tf(float x) {
    unsigned u;
    asm("cvt.rna.tf32.f32 %0, %1;" : "=r"(u) : "f"(x));
    return u;
}

__device__ __forceinline__ void mma8(float c[4], const unsigned a[4], const unsigned b[2]) {
    asm volatile(
        "mma.sync.aligned.m16n8k8.row.col.f32.tf32.tf32.f32 "
        "{%0,%1,%2,%3}, {%4,%5,%6,%7}, {%8,%9}, {%0,%1,%2,%3};\n"
        : "+f"(c[0]), "+f"(c[1]), "+f"(c[2]), "+f"(c[3])
        : "r"(a[0]), "r"(a[1]), "r"(a[2]), "r"(a[3]), "r"(b[0]), "r"(b[1]));
}

__device__ __forceinline__ void mma16(float c[4], const unsigned a[4], const unsigned b[2]) {
    asm volatile(
        "mma.sync.aligned.m16n8k16.row.col.f32.bf16.bf16.f32 "
        "{%0,%1,%2,%3}, {%4,%5,%6,%7}, {%8,%9}, {%0,%1,%2,%3};\n"
        : "+f"(c[0]), "+f"(c[1]), "+f"(c[2]), "+f"(c[3])
        : "r"(a[0]), "r"(a[1]), "r"(a[2]), "r"(a[3]), "r"(b[0]), "r"(b[1]));
}

__device__ __forceinline__ void split2(float x, unsigned short &hh, unsigned short &ll) {
    __nv_bfloat16 bh = __float2bfloat16(x);
    float hf = __bfloat162float(bh);
    __nv_bfloat16 bl = __float2bfloat16(x - hf);
    hh = __bfloat16_as_ushort(bh);
    ll = __bfloat16_as_ushort(bl);
}

__device__ __forceinline__ unsigned bfbits(float x) {
    return (unsigned)__bfloat16_as_ushort(__float2bfloat16(x));
}
__device__ __forceinline__ float bfval(float x) {
    return __bfloat162float(__float2bfloat16(x));
}
__device__ __forceinline__ unsigned packsplit(float x, float y, unsigned &lo) {
    float xh = bfval(x), yh = bfval(y);
    unsigned hi = bfbits(x) | (bfbits(y) << 16);
    lo = bfbits(x - xh) | (bfbits(y - yh) << 16);
    return hi;
}

__device__ __forceinline__ void cp16(void* dst_smem, const void* src, bool pred) {
    unsigned saddr = (unsigned)__cvta_generic_to_shared(dst_smem);
    int sz = pred ? 16 : 0;
    asm volatile("cp.async.cg.shared.global [%0], [%1], 16, %2;\n"
                 :: "r"(saddr), "l"(src), "r"(sz));
}

// ---------------- preconvert: f32 -> tf32 bits (optionally A-permuted) -------
struct CvtArgs {
    const float* src[9];
    unsigned*    dst[9];
    int tstart[10];
    int perm[9];
};

__global__ __launch_bounds__(256)
void cvt_kernel(CvtArgs ca)
{
    int g = 0;
    while ((int)blockIdx.x >= ca.tstart[g + 1]) g++;
    int idx = (blockIdx.x - ca.tstart[g]) * 1024 + threadIdx.x * 4;
    float4 v = *(const float4*)&ca.src[g][idx];
    if (!ca.perm[g]) {
        uint4 u = make_uint4(f2tf(v.x), f2tf(v.y), f2tf(v.z), f2tf(v.w));
        *(uint4*)&ca.dst[g][idx] = u;
    } else {
        int b8 = idx & ~7;
        int c0 = idx & 7;             // 0 or 4
        unsigned* d = ca.dst[g] + b8;
        d[pa8(c0 + 0)] = f2tf(v.x);
        d[pa8(c0 + 1)] = f2tf(v.y);
        d[pa8(c0 + 2)] = f2tf(v.z);
        d[pa8(c0 + 3)] = f2tf(v.w);
    }
}

// ---------------- grouped tf32 GEMM with cp.async pipeline -------------------
// A is tf32-bit u32, k-pair-permuted; B is tf32-bit u32 plain.
// modes: 0 = f32 row-major (guarded), 1 = bf16 hi/lo head-split 192,
//        2 = f32 head-split 128, 3 = tf32-bits row-major A-permuted
#define GSTAGES 3
#define GEMM_SMEM (GSTAGES * (2560 + 2176) * 4)

struct GroupArgs {
    const unsigned* A[4];
    const unsigned* B[4];
    void*        C[4];
    void*        Clo[4];
    int K[4];
    int N[4];
    int mode[4];
    int tstart[5];
};

__global__ __launch_bounds__(256, 2)
void mma_gemm_grouped(GroupArgs ga)
{
    extern __shared__ unsigned gsm[];
    unsigned* As = gsm;                      // [st][128][20]
    unsigned* Bs = gsm + GSTAGES * 2560;     // [st][16][136]

    int g = 0;
    while (blockIdx.y >= (unsigned)ga.tstart[g + 1]) g++;
    const unsigned* __restrict__ A = ga.A[g];
    const unsigned* __restrict__ B = ga.B[g];
    const int K = ga.K[g];
    const int N = ga.N[g];
    const int mode = ga.mode[g];

    const int tid  = threadIdx.x;
    const int lane = tid & 31;
    const int warp = tid >> 5;
    const int wm   = warp & 1;
    const int wn   = warp >> 1;
    const int m0   = blockIdx.x * 128;
    const int n0   = (blockIdx.y - ga.tstart[g]) * 128;
    const int fr   = lane >> 2;
    const int fc   = lane & 3;

    float acc[4][4][4];
#pragma unroll
    for (int mt = 0; mt < 4; mt++)
#pragma unroll
        for (int nt = 0; nt < 4; nt++)
#pragma unroll
            for (int i = 0; i < 4; i++) acc[mt][nt][i] = 0.f;

    const int rowA0 = (tid + 0)   >> 2;   const int kcA0 = ((tid + 0)   & 3) * 4;
    const int rowA1 = (tid + 256) >> 2;   const int kcA1 = ((tid + 256) & 3) * 4;
    const int kkB0  = (tid + 0)   >> 5;   const int c4B0 = ((tid + 0)   & 31) * 4;
    const int kkB1  = (tid + 256) >> 5;   const int c4B1 = ((tid + 256) & 31) * 4;
    const bool pb0 = (n0 + c4B0 < N);
    const bool pb1 = (n0 + c4B1 < N);

    const int ktiles = K >> 4;

#define GLOAD(kt, st)                                                           \
    {                                                                           \
        cp16(&As[(st) * 2560 + rowA0 * 20 + kcA0],                              \
             &A[(size_t)(m0 + rowA0) * K + (kt) * 16 + kcA0], true);            \
        cp16(&As[(st) * 2560 + rowA1 * 20 + kcA1],                              \
             &A[(size_t)(m0 + rowA1) * K + (kt) * 16 + kcA1], true);            \
        cp16(&Bs[(st) * 2176 + kkB0 * 136 + c4B0],                              \
             &B[(size_t)((kt) * 16 + kkB0) * N + n0 + c4B0], pb0);              \
        cp16(&Bs[(st) * 2176 + kkB1 * 136 + c4B1],                              \
             &B[(size_t)((kt) * 16 + kkB1) * N + n0 + c4B1], pb1);              \
    }

#pragma unroll
    for (int s = 0; s < GSTAGES - 1; s++) {
        GLOAD(s, s);
        asm volatile("cp.async.commit_group;\n");
    }

#pragma unroll 1
    for (int i = 0; i < ktiles; i++) {
        asm volatile("cp.async.wait_group %0;\n" :: "n"(GSTAGES - 2));
        __syncthreads();
        int nf = i + GSTAGES - 1;
        if (nf < ktiles) GLOAD(nf, nf % GSTAGES);
        asm volatile("cp.async.commit_group;\n");

        const unsigned* Asb = As + (i % GSTAGES) * 2560;
        const unsigned* Bsb = Bs + (i % GSTAGES) * 2176;
#pragma unroll
        for (int ks = 0; ks < 2; ks++) {
            unsigned af[4][4], bf[4][2];
#pragma unroll
            for (int mt = 0; mt < 4; mt++) {
                int mr = wm * 64 + mt * 16 + fr;
                uint2 p0 = *(const uint2*)&Asb[mr * 20 + ks * 8 + 2 * fc];
                uint2 p1 = *(const uint2*)&Asb[(mr + 8) * 20 + ks * 8 + 2 * fc];
                af[mt][0] = p0.x; af[mt][1] = p1.x; af[mt][2] = p0.y; af[mt][3] = p1.y;
            }
#pragma unroll
            for (int nt = 0; nt < 4; nt++) {
                int nc = wn * 32 + nt * 8 + fr;
                bf[nt][0] = Bsb[(ks * 8 + fc) * 136 + nc];
                bf[nt][1] = Bsb[(ks * 8 + fc + 4) * 136 + nc];
            }
#pragma unroll
            for (int mt = 0; mt < 4; mt++)
#pragma unroll
                for (int nt = 0; nt < 4; nt++)
                    mma8(acc[mt][nt], af[mt], bf[nt]);
        }
    }
#undef GLOAD

    // ---- epilogue ----
#pragma unroll
    for (int mt = 0; mt < 4; mt++) {
#pragma unroll
        for (int nt = 0; nt < 4; nt++) {
            int row = m0 + wm * 64 + mt * 16 + fr;
            int col = n0 + wn * 32 + nt * 8 + fc * 2;
            if (mode == 0) {
                float* Cf = (float*)ga.C[g];
                if (col < N) {
                    *(float2*)&Cf[(size_t)row * N + col] =
                        make_float2(acc[mt][nt][0], acc[mt][nt][1]);
                    *(float2*)&Cf[(size_t)(row + 8) * N + col] =
                        make_float2(acc[mt][nt][2], acc[mt][nt][3]);
                }
            } else if (mode == 1) {
                unsigned short* CH = (unsigned short*)ga.C[g];
                unsigned short* CL = (unsigned short*)ga.Clo[g];
                int hh = col >> 7, d = col & 127;
                int dp = (d & ~15) | pi16e(d & 15);
                size_t b0 = ((size_t)(hh * S_LEN + row)) * DQK + dp;
                size_t b1 = ((size_t)(hh * S_LEN + row + 8)) * DQK + dp;
                unsigned lo, hi;
                hi = packsplit(acc[mt][nt][0], acc[mt][nt][1], lo);
                *(unsigned*)&CH[b0] = hi; *(unsigned*)&CL[b0] = lo;
                hi = packsplit(acc[mt][nt][2], acc[mt][nt][3], lo);
                *(unsigned*)&CH[b1] = hi; *(unsigned*)&CL[b1] = lo;
            } else if (mode == 2) {
                float* Cf = (float*)ga.C[g];
                int hh = col >> 7, d = col & 127;
                *(float2*)&Cf[(size_t)((hh * S_LEN) + row)     * HD + d] =
                    make_float2(acc[mt][nt][0], acc[mt][nt][1]);
                *(float2*)&Cf[(size_t)((hh * S_LEN) + row + 8) * HD + d] =
                    make_float2(acc[mt][nt][2], acc[mt][nt][3]);
            } else {
                unsigned* Cu = (unsigned*)ga.C[g];
                int base = col & ~7;
                int o0 = pa8(col & 7);          // col even -> pair offsets o0, o0+2
                Cu[(size_t)row * N + base + o0]     = f2tf(acc[mt][nt][0]);
                Cu[(size_t)row * N + base + o0 + 2] = f2tf(acc[mt][nt][1]);
                Cu[(size_t)(row + 8) * N + base + o0]     = f2tf(acc[mt][nt][2]);
                Cu[(size_t)(row + 8) * N + base + o0 + 2] = f2tf(acc[mt][nt][3]);
            }
        }
    }
}

// ---------------- prep kernels -----------------------------------------------
__global__ void rope_q_kernel()
{
    int idx = blockIdx.x * blockDim.x + threadIdx.x;
    if (idx >= S_LEN * NH * 32) return;
    int i = idx & 31;
    int h = (idx >> 5) & 15;
    int t = idx >> 9;
    float invf = powf(10000.0f, -(2.0f * i) / 64.0f);
    float ang = (float)t * invf;
    float s, c;
    sincosf(ang, &s, &c);
    const float* x = g_qR + (size_t)t * (NH * DR) + h * DR;
    float x1 = x[i], x2 = x[i + 32];
    float r1 = x1 * c - x2 * s;
    float r2 = x2 * c + x1 * s;
    size_t base = ((size_t)(h * S_LEN + t)) * DQK;
    int d1 = 128 + i, d2 = 160 + i;
    int d1p = (d1 & ~15) | pi16(d1 & 15);
    int d2p = (d2 & ~15) | pi16(d2 & 15);
    unsigned short hh, ll;
    split2(r1, hh, ll); g_QH[base + d1p] = hh; g_QL[base + d1p] = ll;
    split2(r2, hh, ll); g_QH[base + d2p] = hh; g_QL[base + d2p] = ll;
}

__global__ void rope_k_kernel()
{
    int idx = blockIdx.x * blockDim.x + threadIdx.x;
    if (idx >= S_LEN * 32) return;
    int i = idx & 31;
    int t = idx >> 5;
    float invf = powf(10000.0f, -(2.0f * i) / 64.0f);
    float ang = (float)t * invf;
    float s, c;
    sincosf(ang, &s, &c);
    const float* x = g_kR + (size_t)t * DR;
    float r1 = x[i] * c - x[i + 32] * s;
    float r2 = x[i + 32] * c + x[i] * s;
    unsigned short h1, l1, h2, l2;
    split2(r1, h1, l1);
    split2(r2, h2, l2);
    int d1 = 128 + i, d2 = 160 + i;
    int d1p = (d1 & ~15) | pi16(d1 & 15);
    int d2p = (d2 & ~15) | pi16(d2 & 15);
#pragma unroll
    for (int h = 0; h < NH; h++) {
        size_t base = ((size_t)(h * S_LEN + t)) * DQK;
        g_KH[base + d1p] = h1; g_KL[base + d1p] = l1;
        g_KH[base + d2p] = h2; g_KL[base + d2p] = l2;
    }
}

__global__ __launch_bounds__(256)
void vtrans_kernel()
{
    __shared__ float sv[64][133];
    const int h  = blockIdx.y;
    const int s0 = blockIdx.x * 64;
    const int tid = threadIdx.x;
    const float* src = g_Vb + ((size_t)h * S_LEN + s0) * HD;
#pragma unroll
    for (int i = 0; i < 8; i++) {
        int idx = tid + i * 256;
        int r = idx >> 5, c4 = (idx & 31) * 4;
        float4 v = *(const float4*)&src[r * HD + c4];
        sv[r][c4] = v.x; sv[r][c4 + 1] = v.y; sv[r][c4 + 2] = v.z; sv[r][c4 + 3] = v.w;
    }
    __syncthreads();
    int sl = tid & 63, d0 = tid >> 6;
    int sp = s0 + ((sl & ~15) | pi16(sl & 15));
#pragma unroll
    for (int dd = 0; dd < 32; dd++) {
        int d = d0 * 32 + dd;
        unsigned short hh, ll;
        split2(sv[sl][d], hh, ll);
        size_t o = ((size_t)(h * HD + d)) * S_LEN + sp;
        g_VTH[o] = hh;
        g_VTL[o] = ll;
    }
}

// ---------------- bf16x3 flash attention: cp.async-pipelined K/V -------------
#define ATTN_SMEM 200704

__global__ __launch_bounds__(256, 1)
void attn_mma_kernel()
{
    extern __shared__ char smraw[];
    unsigned short* QH  = (unsigned short*)(smraw);
    unsigned short* QL  = (unsigned short*)(smraw + 53248);
    unsigned short* KH  = (unsigned short*)(smraw + 106496);
    unsigned short* KL  = (unsigned short*)(smraw + 133120);
    unsigned short* VTH = (unsigned short*)(smraw + 159744);
    unsigned short* VTL = (unsigned short*)(smraw + 180224);

    const int bid  = blockIdx.x;
    const int mb   = 15 - (bid >> 4);
    const int h    = bid & 15;
    const int m0   = mb * 128;
    const int tid  = threadIdx.x;
    const int lane = tid & 31;
    const int warp = tid >> 5;
    const int g = lane >> 2, t = lane & 3;

    const uint4* KHg = (const uint4*)(g_KH + (size_t)h * S_LEN * DQK);
    const uint4* KLg = (const uint4*)(g_KL + (size_t)h * S_LEN * DQK);
    const uint4* VHg = (const uint4*)(g_VTH + (size_t)h * HD * S_LEN);
    const uint4* VLg = (const uint4*)(g_VTL + (size_t)h * HD * S_LEN);
    uint4* KH4 = (uint4*)KH;
    uint4* KL4 = (uint4*)KL;
    uint4* VH4 = (uint4*)VTH;
    uint4* VL4 = (uint4*)VTL;

#define CPK(nn)                                                                 \
    {                                                                           \
        const uint4* sH = KHg + (size_t)(nn) * 24;                              \
        const uint4* sL = KLg + (size_t)(nn) * 24;                              \
        _Pragma("unroll")                                                       \
        for (int i = 0; i < 6; i++) {                                           \
            int idx = tid + i * 256;                                            \
            int r = idx / 24, u = idx - r * 24;                                 \
            cp16(&KH4[r * 26 + u], &sH[idx], true);                             \
            cp16(&KL4[r * 26 + u], &sL[idx], true);                             \
        }                                                                       \
    }
#define CPV(nn)                                                                 \
    {                                                                           \
        const uint4* sH = VHg + ((nn) >> 3);                                    \
        const uint4* sL = VLg + ((nn) >> 3);                                    \
        _Pragma("unroll")                                                       \
        for (int i = 0; i < 4; i++) {                                           \
            int idx = tid + i * 256;                                            \
            int d = idx >> 3, u = idx & 7;                                      \
            cp16(&VH4[d * 10 + u], &sH[d * 256 + u], true);                     \
            cp16(&VL4[d * 10 + u], &sL[d * 256 + u], true);                     \
        }                                                                       \
    }

    // prefetch tile 0
    CPK(0);
    asm volatile("cp.async.commit_group;\n");
    CPV(0);
    asm volatile("cp.async.commit_group;\n");

    // stage Q while tile 0 lands
    {
        const uint4* sH = (const uint4*)(g_QH + ((size_t)h * S_LEN + m0) * DQK);
        const uint4* sL = (const uint4*)(g_QL + ((size_t)h * S_LEN + m0) * DQK);
        uint4* dH = (uint4*)QH;
        uint4* dL = (uint4*)QL;
#pragma unroll
        for (int i = 0; i < 12; i++) {
            int idx = tid + i * 256;
            int r = idx / 24, u = idx - r * 24;
            dH[r * 26 + u] = sH[idx];
            dL[r * 26 + u] = sL[idx];
        }
    }

    float oacc[16][4];
#pragma unroll
    for (int nt = 0; nt < 16; nt++)
#pragma unroll
        for (int c = 0; c < 4; c++) oacc[nt][c] = 0.f;

    float mrow[2] = {-1e30f, -1e30f};
    float lrow[2] = {0.f, 0.f};

    const float scale = 0.07216878364870322f;
    const int ntiles = 2 * mb + 2;

    asm volatile("cp.async.wait_group 0;\n");
    __syncthreads();

#pragma unroll 1
    for (int tile = 0; tile < ntiles; tile++) {
        const int n0 = tile * 64;
        const int npf = (tile + 1 < ntiles) ? (tile + 1) * 64 : 0;

        // ---- S = Q K^T ----
        float sacc[8][4];
#pragma unroll
        for (int nt = 0; nt < 8; nt++)
#pragma unroll
            for (int c = 0; c < 4; c++) sacc[nt][c] = 0.f;

#pragma unroll
        for (int kt = 0; kt < 12; kt++) {
            unsigned ah[4], al[4];
            {
                int rb = (warp * 16 + g) * 208 + kt * 16 + 4 * t;
                uint2 a0 = *(const uint2*)&QH[rb];
                uint2 a1 = *(const uint2*)&QH[rb + 8 * 208];
                ah[0] = a0.x; ah[1] = a1.x; ah[2] = a0.y; ah[3] = a1.y;
                uint2 b0 = *(const uint2*)&QL[rb];
                uint2 b1 = *(const uint2*)&QL[rb + 8 * 208];
                al[0] = b0.x; al[1] = b1.x; al[2] = b0.y; al[3] = b1.y;
            }
#pragma unroll
            for (int nt = 0; nt < 8; nt++) {
                int nb = (nt * 8 + g) * 208 + kt * 16 + 4 * t;
                uint2 kb = *(const uint2*)&KH[nb];
                uint2 kl = *(const uint2*)&KL[nb];
                unsigned bh[2] = {kb.x, kb.y};
                unsigned bl[2] = {kl.x, kl.y};
                mma16(sacc[nt], ah, bh);
                mma16(sacc[nt], ah, bl);
                mma16(sacc[nt], al, bh);
            }
        }

        // V of this tile is guaranteed complete; all warps done reading K
        asm volatile("cp.async.wait_group 0;\n");
        __syncthreads();
        // prefetch next K (overlaps softmax + PV)
        CPK(npf);
        asm volatile("cp.async.commit_group;\n");

        // ---- scale + causal mask ----
#pragma unroll
        for (int nt = 0; nt < 8; nt++)
#pragma unroll
            for (int c = 0; c < 4; c++) {
                int col = n0 + nt * 8 + 2 * t + (c & 1);
                int row = m0 + warp * 16 + g + (c >> 1) * 8;
                float v = sacc[nt][c] * scale;
                if (col > row) v = -1e30f;
                sacc[nt][c] = v;
            }

        // ---- warp-local online softmax ----
        float alpha_[2];
#pragma unroll
        for (int hf = 0; hf < 2; hf++) {
            float pm = -1e30f;
#pragma unroll
            for (int nt = 0; nt < 8; nt++)
                pm = fmaxf(pm, fmaxf(sacc[nt][hf * 2], sacc[nt][hf * 2 + 1]));
            pm = fmaxf(pm, __shfl_xor_sync(0xffffffffu, pm, 1));
            pm = fmaxf(pm, __shfl_xor_sync(0xffffffffu, pm, 2));
            float mnew = fmaxf(mrow[hf], pm);
            alpha_[hf] = __expf(mrow[hf] - mnew);
            mrow[hf] = mnew;
            float ps = 0.f;
#pragma unroll
            for (int nt = 0; nt < 8; nt++)
#pragma unroll
                for (int k2 = 0; k2 < 2; k2++) {
                    int c = hf * 2 + k2;
                    float p = __expf(sacc[nt][c] - mnew);
                    sacc[nt][c] = p;
                    ps += p;
                }
            lrow[hf] = lrow[hf] * alpha_[hf] + ps;
        }
#pragma unroll
        for (int nt = 0; nt < 16; nt++)
#pragma unroll
            for (int c = 0; c < 4; c++)
                oacc[nt][c] *= alpha_[c >> 1];

        // ---- O += P V ----
#pragma unroll
        for (int kt = 0; kt < 4; kt++) {
            unsigned aph[4], apl[4];
            aph[0] = packsplit(sacc[2 * kt][0],     sacc[2 * kt][1],     apl[0]);
            aph[1] = packsplit(sacc[2 * kt][2],     sacc[2 * kt][3],     apl[1]);
            aph[2] = packsplit(sacc[2 * kt + 1][0], sacc[2 * kt + 1][1], apl[2]);
            aph[3] = packsplit(sacc[2 * kt + 1][2], sacc[2 * kt + 1][3], apl[3]);
#pragma unroll
            for (int nt = 0; nt < 16; nt++) {
                int vb = (nt * 8 + g) * 80 + kt * 16 + 4 * t;
                uint2 vh = *(const uint2*)&VTH[vb];
                uint2 vl = *(const uint2*)&VTL[vb];
                unsigned bh[2] = {vh.x, vh.y};
                unsigned bl[2] = {vl.x, vl.y};
                mma16(oacc[nt], aph, bh);
                mma16(oacc[nt], aph, bl);
                mma16(oacc[nt], apl, bh);
            }
        }

        // all warps done reading V; prefetch next V (overlaps next S)
        __syncthreads();
        CPV(npf);
        asm volatile("cp.async.commit_group;\n");
        // ensure next K complete before next S (leaves V group in flight)
        asm volatile("cp.async.wait_group 1;\n");
        __syncthreads();
    }
#undef CPK
#undef CPV

    // ---- epilogue: quad-reduce l, store AO as tf32 bits (A-permuted) ----
#pragma unroll
    for (int hf = 0; hf < 2; hf++) {
        float lq = lrow[hf];
        lq += __shfl_xor_sync(0xffffffffu, lq, 1);
        lq += __shfl_xor_sync(0xffffffffu, lq, 2);
        float inv = 1.f / lq;
        int row = m0 + warp * 16 + hf * 8 + g;
#pragma unroll
        for (int nt = 0; nt < 16; nt++) {
            int col = nt * 8 + 2 * t;
            int base = col & ~7;
            int o0 = pa8(col & 7);
            unsigned* dst = g_AO + (size_t)row * (NH * HD) + h * HD + base;
            dst[o0]     = f2tf(oacc[nt][hf * 2]     * inv);
            dst[o0 + 2] = f2tf(oacc[nt][hf * 2 + 1] * inv);
        }
    }
}

// ---------------- launch ----------------------------------------------------
extern "C" void kernel_launch(void* const* d_in, const int* in_sizes, int n_in,
                              void* d_out, int out_size)
{
    const float* X     = (const float*)d_in[0];
    const float* W_DKV = (const float*)d_in[2];
    const float* W_UK  = (const float*)d_in[3];
    const float* W_UV  = (const float*)d_in[4];
    const float* W_DQ  = (const float*)d_in[5];
    const float* W_UQ  = (const float*)d_in[6];
    const float* W_QR  = (const float*)d_in[7];
    const float* W_KR  = (const float*)d_in[8];
    const float* W_O   = (const float*)d_in[9];
    float* out = (float*)d_out;

    unsigned *Xt, *Wdkv, *Wuk, *Wuv, *Wdq, *Wuq, *Wqr, *Wkr, *Wo;
    unsigned *cKVt, *cQt, *AO;
    float *qR, *kR, *Vb;
    unsigned short *QHp, *QLp, *KHp, *KLp;
    cudaGetSymbolAddress((void**)&Xt,   g_Xt);
    cudaGetSymbolAddress((void**)&Wdkv, g_Wdkv);
    cudaGetSymbolAddress((void**)&Wuk,  g_Wuk);
    cudaGetSymbolAddress((void**)&Wuv,  g_Wuv);
    cudaGetSymbolAddress((void**)&Wdq,  g_Wdq);
    cudaGetSymbolAddress((void**)&Wuq,  g_Wuq);
    cudaGetSymbolAddress((void**)&Wqr,  g_Wqr);
    cudaGetSymbolAddress((void**)&Wkr,  g_Wkr);
    cudaGetSymbolAddress((void**)&Wo,   g_Wo);
    cudaGetSymbolAddress((void**)&cKVt, g_cKVt);
    cudaGetSymbolAddress((void**)&cQt,  g_cQt);
    cudaGetSymbolAddress((void**)&AO,   g_AO);
    cudaGetSymbolAddress((void**)&qR,   g_qR);
    cudaGetSymbolAddress((void**)&kR,   g_kR);
    cudaGetSymbolAddress((void**)&Vb,   g_Vb);
    cudaGetSymbolAddress((void**)&QHp,  g_QH);
    cudaGetSymbolAddress((void**)&QLp,  g_QL);
    cudaGetSymbolAddress((void**)&KHp,  g_KH);
    cudaGetSymbolAddress((void**)&KLp,  g_KL);

    dim3 blk(256);

    // 0) preconvert all GEMM operands to tf32 bits (X is an A-operand: permuted)
    {
        CvtArgs ca = {};
        const float* srcs[9] = {X, W_DKV, W_UK, W_UV, W_DQ, W_UQ, W_QR, W_KR, W_O};
        unsigned* dsts[9] = {Xt, Wdkv, Wuk, Wuv, Wdq, Wuq, Wqr, Wkr, Wo};
        int sizes[9] = {S_LEN * HID_D, HID_D * CKV, CKV * NH * HD, CKV * NH * HD,
                        HID_D * CQ, CQ * NH * HD, CQ * NH * DR, HID_D * DR,
                        NH * HD * HID_D};
        int acc = 0;
        for (int i = 0; i < 9; i++) {
            ca.src[i] = srcs[i];
            ca.dst[i] = dsts[i];
            ca.tstart[i] = acc;
            ca.perm[i] = (i == 0) ? 1 : 0;
            acc += sizes[i] / 1024;
        }
        ca.tstart[9] = acc;
        cvt_kernel<<<acc, blk>>>(ca);
    }

    cudaFuncSetAttribute(mma_gemm_grouped,
                         cudaFuncAttributeMaxDynamicSharedMemorySize, GEMM_SMEM);

    // P1: Xt @ {Wdq->cQt(tf32 perm), Wdkv->cKVt(tf32 perm), Wkr->kR(f32)}
    {
        GroupArgs ga = {};
        ga.A[0] = Xt; ga.B[0] = Wdq;  ga.C[0] = cQt;  ga.K[0] = HID_D; ga.N[0] = CQ;  ga.mode[0] = 3;
        ga.A[1] = Xt; ga.B[1] = Wdkv; ga.C[1] = cKVt; ga.K[1] = HID_D; ga.N[1] = CKV; ga.mode[1] = 3;
        ga.A[2] = Xt; ga.B[2] = Wkr;  ga.C[2] = kR;   ga.K[2] = HID_D; ga.N[2] = DR;  ga.mode[2] = 0;
        ga.tstart[0] = 0; ga.tstart[1] = 12; ga.tstart[2] = 16; ga.tstart[3] = 17; ga.tstart[4] = 17;
        mma_gemm_grouped<<<dim3(16, 17), blk, GEMM_SMEM>>>(ga);
    }
    // P2: {Wuq->bf16 Q, Wqr->qR(f32), Wuk->bf16 K, Wuv->V(f32)}
    {
        GroupArgs ga = {};
        ga.A[0] = cQt;  ga.B[0] = Wuq; ga.C[0] = QHp; ga.Clo[0] = QLp; ga.K[0] = CQ;  ga.N[0] = NH * HD; ga.mode[0] = 1;
        ga.A[1] = cQt;  ga.B[1] = Wqr; ga.C[1] = qR;                   ga.K[1] = CQ;  ga.N[1] = NH * DR; ga.mode[1] = 0;
        ga.A[2] = cKVt; ga.B[2] = Wuk; ga.C[2] = KHp; ga.Clo[2] = KLp; ga.K[2] = CKV; ga.N[2] = NH * HD; ga.mode[2] = 1;
        ga.A[3] = cKVt; ga.B[3] = Wuv; ga.C[3] = Vb;                   ga.K[3] = CKV; ga.N[3] = NH * HD; ga.mode[3] = 2;
        ga.tstart[0] = 0; ga.tstart[1] = 16; ga.tstart[2] = 24; ga.tstart[3] = 40; ga.tstart[4] = 56;
        mma_gemm_grouped<<<dim3(16, 56), blk, GEMM_SMEM>>>(ga);
    }

    rope_q_kernel<<<(S_LEN * NH * 32) / 256, 256>>>();
    rope_k_kernel<<<(S_LEN * 32) / 256, 256>>>();
    vtrans_kernel<<<dim3(S_LEN / 64, NH), 256>>>();

    cudaFuncSetAttribute(attn_mma_kernel, cudaFuncAttributeMaxDynamicSharedMemorySize, ATTN_SMEM);
    attn_mma_kernel<<<256, 256, ATTN_SMEM>>>();

    // WO: AO(tf32 perm) @ Wo -> out (f32)
    {
        GroupArgs ga = {};
        ga.A[0] = AO; ga.B[0] = Wo; ga.C[0] = out; ga.K[0] = NH * HD; ga.N[0] = HID_D; ga.mode[0] = 0;
        ga.tstart[0] = 0; ga.tstart[1] = 16; ga.tstart[2] = 16; ga.tstart[3] = 16; ga.tstart[4] = 16;
        mma_gemm_grouped<<<dim3(16, 16), blk, GEMM_SMEM>>>(ga);
    }
}